// round 10
// baseline (speedup 1.0000x reference)
#include <cuda_runtime.h>
#include <cuda_bf16.h>
#include <math.h>

#define SQ 2048
#define DM 1024
#define NH 16
#define HD 64

// ---------------- device scratch (no allocs) ----------------
static __device__ float g_cos[SQ * 32];
static __device__ float g_sin[SQ * 32];

static __device__ __nv_bfloat16 g_xh[SQ * DM],  g_xl[SQ * DM];
static __device__ __nv_bfloat16 g_Wqh[DM * DM], g_Wql[DM * DM];
static __device__ __nv_bfloat16 g_Wkh[DM * DM], g_Wkl[DM * DM];
static __device__ __nv_bfloat16 g_Wvh[DM * DM], g_Wvl[DM * DM];
static __device__ __nv_bfloat16 g_Woh[DM * DM], g_Wol[DM * DM];
static __device__ __nv_bfloat16 g_qh[NH * SQ * HD], g_ql[NH * SQ * HD];
static __device__ __nv_bfloat16 g_kh[NH * SQ * HD], g_kl[NH * SQ * HD];
static __device__ __nv_bfloat16 g_vh[NH * SQ * HD], g_vl[NH * SQ * HD];
static __device__ __nv_bfloat16 g_oh[SQ * DM],  g_ol[SQ * DM];

// ---------------- helpers ----------------
__device__ __forceinline__ unsigned sptr(const void* p) {
    return (unsigned)__cvta_generic_to_shared(p);
}
__device__ __forceinline__ void cpa16(void* dst, const void* src) {
    asm volatile("cp.async.cg.shared.global [%0], [%1], 16;"
                 :: "r"(sptr(dst)), "l"(src));
}
__device__ __forceinline__ void cp_commit() {
    asm volatile("cp.async.commit_group;");
}
template <int N>
__device__ __forceinline__ void cp_wait() {
    asm volatile("cp.async.wait_group %0;" :: "n"(N));
}
__device__ __forceinline__ void ldsm4(unsigned& r0, unsigned& r1, unsigned& r2,
                                      unsigned& r3, unsigned a) {
    asm volatile("ldmatrix.sync.aligned.m8n8.x4.shared.b16 {%0,%1,%2,%3},[%4];"
                 : "=r"(r0), "=r"(r1), "=r"(r2), "=r"(r3) : "r"(a));
}
__device__ __forceinline__ void ldsm4t(unsigned& r0, unsigned& r1, unsigned& r2,
                                       unsigned& r3, unsigned a) {
    asm volatile("ldmatrix.sync.aligned.m8n8.x4.trans.shared.b16 {%0,%1,%2,%3},[%4];"
                 : "=r"(r0), "=r"(r1), "=r"(r2), "=r"(r3) : "r"(a));
}
__device__ __forceinline__ void mma16(float* c, const unsigned a[4],
                                      unsigned b0, unsigned b1) {
    asm volatile(
        "mma.sync.aligned.m16n8k16.row.col.f32.bf16.bf16.f32 "
        "{%0,%1,%2,%3},{%4,%5,%6,%7},{%8,%9},{%0,%1,%2,%3};"
        : "+f"(c[0]), "+f"(c[1]), "+f"(c[2]), "+f"(c[3])
        : "r"(a[0]), "r"(a[1]), "r"(a[2]), "r"(a[3]), "r"(b0), "r"(b1));
}
__device__ __forceinline__ void splitf(float x, __nv_bfloat16& h, __nv_bfloat16& l) {
    h = __float2bfloat16(x);
    l = __float2bfloat16(x - __bfloat162float(h));
}
__device__ __forceinline__ unsigned pkbf(__nv_bfloat16 a, __nv_bfloat16 b) {
    __nv_bfloat162 t = __halves2bfloat162(a, b);
    return *reinterpret_cast<unsigned*>(&t);
}
__device__ __forceinline__ void split2(float x, float y, unsigned& h, unsigned& l) {
    __nv_bfloat16 hx, lx, hy, ly;
    splitf(x, hx, lx);
    splitf(y, hy, ly);
    h = pkbf(hx, hy);
    l = pkbf(lx, ly);
}

// ---------------------------------------------------------------------------
// RoPE cos/sin table (fp64-accurate)
// ---------------------------------------------------------------------------
__global__ void rope_table(const float* __restrict__ inv_freq)
{
    const int idx = blockIdx.x * 256 + threadIdx.x;
    const int s = idx >> 5;
    const int j = idx & 31;
    const double f = (double)s * (double)inv_freq[j];
    g_cos[idx] = (float)cos(f);
    g_sin[idx] = (float)sin(f);
}

// ---------------------------------------------------------------------------
// Fused split: one launch splits x + all 4 weight matrices into hi/lo bf16.
// blockIdx.y selects the target; grid.x sized for the largest (x).
// ---------------------------------------------------------------------------
__global__ void split_all(const float* __restrict__ x,
                          const float* __restrict__ Wq,
                          const float* __restrict__ Wk,
                          const float* __restrict__ Wv,
                          const float* __restrict__ Wo)
{
    const int which = blockIdx.y;
    const float* src;
    __nv_bfloat16* h;
    __nv_bfloat16* l;
    int n4;
    switch (which) {
        case 0: src = x;  h = g_xh;  l = g_xl;  n4 = SQ * DM / 4; break;
        case 1: src = Wq; h = g_Wqh; l = g_Wql; n4 = DM * DM / 4; break;
        case 2: src = Wk; h = g_Wkh; l = g_Wkl; n4 = DM * DM / 4; break;
        case 3: src = Wv; h = g_Wvh; l = g_Wvl; n4 = DM * DM / 4; break;
        default: src = Wo; h = g_Woh; l = g_Wol; n4 = DM * DM / 4; break;
    }
    const int i = blockIdx.x * 256 + threadIdx.x;
    if (i >= n4) return;
    float4 v = reinterpret_cast<const float4*>(src)[i];
    __nv_bfloat16 hh[4], ll[4];
    splitf(v.x, hh[0], ll[0]);
    splitf(v.y, hh[1], ll[1]);
    splitf(v.z, hh[2], ll[2]);
    splitf(v.w, hh[3], ll[3]);
    reinterpret_cast<uint2*>(h)[i] = make_uint2(pkbf(hh[0], hh[1]), pkbf(hh[2], hh[3]));
    reinterpret_cast<uint2*>(l)[i] = make_uint2(pkbf(ll[0], ll[1]), pkbf(ll[2], ll[3]));
}

// ---------------------------------------------------------------------------
// Projection GEMM core (bf16 3-term split, pre-split inputs, cp.async).
// CTA 128x128, BK=32, 512 threads = 16 warps (4m x 4n), warp tile 32x32.
// ---------------------------------------------------------------------------
#define PK 40
#define PBUF (128 * PK)

#define PJ_ISSUE(kt, b) do {                                                   \
    __nv_bfloat16* d0 = smb + (size_t)(b) * 4 * PBUF + cr * PK + cc;           \
    cpa16(d0,            Ah + (size_t)(m0 + cr) * DM + (kt) * 32 + cc);        \
    cpa16(d0 + PBUF,     Al + (size_t)(m0 + cr) * DM + (kt) * 32 + cc);        \
    cpa16(d0 + 2 * PBUF, Wh + (size_t)(n0 + cr) * DM + (kt) * 32 + cc);        \
    cpa16(d0 + 3 * PBUF, Wl + (size_t)(n0 + cr) * DM + (kt) * 32 + cc);        \
    cp_commit();                                                                \
} while (0)

__device__ __forceinline__ void proj_core(
    const __nv_bfloat16* __restrict__ Ah, const __nv_bfloat16* __restrict__ Al,
    const __nv_bfloat16* __restrict__ Wh, const __nv_bfloat16* __restrict__ Wl,
    int m0, int n0, __nv_bfloat16* smb, float acc[2][4][4], int tid)
{
    const int lane = tid & 31;
    const int wid = tid >> 5;
    const int wm = (wid & 3) * 32;
    const int wn = (wid >> 2) * 32;
    const int lrow = lane & 15;
    const int lcol = (lane >> 4) * 8;
    const int cr = tid >> 2;          // 0..127
    const int cc = (tid & 3) * 8;     // 0,8,16,24

#pragma unroll
    for (int mt = 0; mt < 2; mt++)
#pragma unroll
        for (int nt = 0; nt < 4; nt++)
#pragma unroll
            for (int r = 0; r < 4; r++) acc[mt][nt][r] = 0.f;

    PJ_ISSUE(0, 0);

    int buf = 0;
    for (int kt = 0; kt < DM / 32; kt++) {
        if (kt + 1 < DM / 32) {
            PJ_ISSUE(kt + 1, buf ^ 1);
            cp_wait<1>();
        } else {
            cp_wait<0>();
        }
        __syncthreads();

        __nv_bfloat16* sAh = smb + (size_t)buf * 4 * PBUF;
        __nv_bfloat16* sAl = sAh + PBUF;
        __nv_bfloat16* sWh = sAh + 2 * PBUF;
        __nv_bfloat16* sWl = sAh + 3 * PBUF;

#pragma unroll
        for (int ks = 0; ks < 2; ks++) {
            unsigned ah[2][4], al[2][4];
#pragma unroll
            for (int mt = 0; mt < 2; mt++) {
                const int off = (wm + mt * 16 + lrow) * PK + ks * 16 + lcol;
                ldsm4(ah[mt][0], ah[mt][1], ah[mt][2], ah[mt][3], sptr(sAh + off));
                ldsm4(al[mt][0], al[mt][1], al[mt][2], al[mt][3], sptr(sAl + off));
            }
#pragma unroll
            for (int ng = 0; ng < 2; ng++) {
                unsigned h0, h1, h2, h3, l0, l1, l2, l3;
                const int off = (wn + ng * 16 + lrow) * PK + ks * 16 + lcol;
                ldsm4(h0, h1, h2, h3, sptr(sWh + off));
                ldsm4(l0, l1, l2, l3, sptr(sWl + off));
#pragma unroll
                for (int mt = 0; mt < 2; mt++) {
                    mma16(acc[mt][2 * ng], ah[mt], h0, h2);
                    mma16(acc[mt][2 * ng], ah[mt], l0, l2);
                    mma16(acc[mt][2 * ng], al[mt], h0, h2);
                    mma16(acc[mt][2 * ng + 1], ah[mt], h1, h3);
                    mma16(acc[mt][2 * ng + 1], ah[mt], l1, l3);
                    mma16(acc[mt][2 * ng + 1], al[mt], h1, h3);
                }
            }
        }
        __syncthreads();
        buf ^= 1;
    }
}

// ---------------------------------------------------------------------------
// Fused QKV GEMM + bias + RoPE + scale; outputs hi/lo bf16 head-layout arrays.
// ---------------------------------------------------------------------------
__global__ void __launch_bounds__(512) qkv_gemm(
    const float* __restrict__ bq, const float* __restrict__ bv)
{
    extern __shared__ __align__(16) __nv_bfloat16 smb[];
    const int tid = threadIdx.x;
    const int z = blockIdx.z;
    const int m0 = blockIdx.y * 128;
    const int n0 = blockIdx.x * 128;

    const __nv_bfloat16* Wh = (z == 0) ? g_Wqh : (z == 1) ? g_Wkh : g_Wvh;
    const __nv_bfloat16* Wl = (z == 0) ? g_Wql : (z == 1) ? g_Wkl : g_Wvl;
    const float* bias = (z == 0) ? bq : (z == 2) ? bv : nullptr;
    __nv_bfloat16* outh = (z == 0) ? g_qh : (z == 1) ? g_kh : g_vh;
    __nv_bfloat16* outl = (z == 0) ? g_ql : (z == 1) ? g_kl : g_vl;

    float acc[2][4][4];
    proj_core(g_xh, g_xl, Wh, Wl, m0, n0, smb, acc, tid);

    const int lane = tid & 31;
    const int wid = tid >> 5;
    const int g = lane >> 2;
    const int t = lane & 3;
    const int wm = (wid & 3) * 32;
    const int wn = (wid >> 2) * 32;
    const float rsc = 0.35355339059327373f;   // 64^(-1/4)

#pragma unroll
    for (int mt = 0; mt < 2; mt++) {
#pragma unroll
        for (int nt = 0; nt < 4; nt++) {
            const int n = n0 + wn + nt * 8 + 2 * t;
            const int hh = n >> 6;
            const int d = n & 63;
            const float b0v = bias ? bias[n] : 0.f;
            const float b1v = bias ? bias[n + 1] : 0.f;
#pragma unroll
            for (int half = 0; half < 2; half++) {
                const int m = m0 + wm + mt * 16 + g + half * 8;
                float a = acc[mt][nt][half * 2 + 0] + b0v;
                float b = acc[mt][nt][half * 2 + 1] + b1v;
                const size_t off = ((size_t)hh * SQ + m) * HD + d;
                unsigned hp, lp;
                if (z < 2) {
                    const int pi = d >> 1;
                    const float c = g_cos[m * 32 + pi];
                    const float s = g_sin[m * 32 + pi];
                    split2(rsc * (a * c - b * s), rsc * (a * s + b * c), hp, lp);
                } else {
                    split2(a, b, hp, lp);
                }
                *reinterpret_cast<unsigned*>(outh + off) = hp;
                *reinterpret_cast<unsigned*>(outl + off) = lp;
            }
        }
    }
}

// ---------------------------------------------------------------------------
// Output projection: out = wv(split) @ Wo^T + bo, fp32 row-major
// ---------------------------------------------------------------------------
__global__ void __launch_bounds__(512) out_gemm(
    const float* __restrict__ bo, float* __restrict__ C)
{
    extern __shared__ __align__(16) __nv_bfloat16 smb[];
    const int tid = threadIdx.x;
    const int m0 = blockIdx.y * 128;
    const int n0 = blockIdx.x * 128;

    float acc[2][4][4];
    proj_core(g_oh, g_ol, g_Woh, g_Wol, m0, n0, smb, acc, tid);

    const int lane = tid & 31;
    const int wid = tid >> 5;
    const int g = lane >> 2;
    const int t = lane & 3;
    const int wm = (wid & 3) * 32;
    const int wn = (wid >> 2) * 32;

#pragma unroll
    for (int mt = 0; mt < 2; mt++) {
#pragma unroll
        for (int nt = 0; nt < 4; nt++) {
            const int n = n0 + wn + nt * 8 + 2 * t;
            const float b0v = bo[n], b1v = bo[n + 1];
#pragma unroll
            for (int half = 0; half < 2; half++) {
                const int m = m0 + wm + mt * 16 + g + half * 8;
                *reinterpret_cast<float2*>(C + (size_t)m * DM + n) =
                    make_float2(acc[mt][nt][half * 2 + 0] + b0v,
                                acc[mt][nt][half * 2 + 1] + b1v);
            }
        }
    }
}

// ---------------------------------------------------------------------------
// Attention. CTA: 1 head x 128 q rows, 256 threads = 8 warps x 16 rows.
// grid = (16 q-tiles, 16 heads) = 256 CTAs; smem 110.6 KB -> 2 CTAs/SM.
// Pre-split bf16 q/k/v via cp.async; K/V tiles double-buffered.
// smem bf16 elems: sQh/sQl[128*72], 2 x {Kh,Kl,Vh,Vl}[64*72]
// ---------------------------------------------------------------------------
#define AS 72
#define A_QH 0
#define A_QL 9216
#define A_KV 18432
#define A_KVB 18432

__global__ void __launch_bounds__(256) attn_kernel(
    const float* __restrict__ mask, const float* __restrict__ Zf,
    float* __restrict__ qk_out)
{
    extern __shared__ __align__(16) __nv_bfloat16 smb[];
    __nv_bfloat16* sQh = smb + A_QH;
    __nv_bfloat16* sQl = smb + A_QL;

    const int tid = threadIdx.x;
    const int lane = tid & 31;
    const int wid = tid >> 5;
    const int g = lane >> 2;
    const int t = lane & 3;
    const int lrow = lane & 15;
    const int lcol = (lane >> 4) * 8;
    const int wr = wid * 16;
    const int h = blockIdx.y;
    const int q0 = blockIdx.x * 128;

    const float zfac = fminf(fmaxf(log1pf(expf(Zf[0])), 1e-5f), 1e-4f);

    // ---- prologue: Q copy (128 rows) + KV tile 0 ----
#pragma unroll
    for (int i = 0; i < 4; i++) {
        const int idx = tid + i * 256;           // 0..1023
        const int r = idx >> 3;
        const int c = (idx & 7) * 8;
        const size_t so = ((size_t)h * SQ + q0 + r) * HD + c;
        cpa16(sQh + r * AS + c, g_qh + so);
        cpa16(sQl + r * AS + c, g_ql + so);
    }
    {
        __nv_bfloat16* kb = smb + A_KV;
#pragma unroll
        for (int i = 0; i < 2; i++) {
            const int idx = tid + i * 256;        // 0..511
            const int r = idx >> 3;
            const int c = (idx & 7) * 8;
            const size_t so = ((size_t)h * SQ + r) * HD + c;
            cpa16(kb +         r * AS + c, g_kh + so);
            cpa16(kb + 4608 +  r * AS + c, g_kl + so);
            cpa16(kb + 9216 +  r * AS + c, g_vh + so);
            cpa16(kb + 13824 + r * AS + c, g_vl + so);
        }
        cp_commit();
    }

    float ofr[8][4];
    float m_i[2], l_i[2];
#pragma unroll
    for (int nt = 0; nt < 8; nt++)
#pragma unroll
        for (int r = 0; r < 4; r++) ofr[nt][r] = 0.f;
    m_i[0] = m_i[1] = -INFINITY;
    l_i[0] = l_i[1] = 0.f;

    const float2* mask2 = reinterpret_cast<const float2*>(mask);
    float2* qk2 = reinterpret_cast<float2*>(qk_out);

    int buf = 0;
    for (int kt = 0; kt < SQ / 64; kt++) {
        if (kt + 1 < SQ / 64) {
            __nv_bfloat16* kb = smb + A_KV + (size_t)(buf ^ 1) * A_KVB;
#pragma unroll
            for (int i = 0; i < 2; i++) {
                const int idx = tid + i * 256;
                const int r = idx >> 3;
                const int c = (idx & 7) * 8;
                const size_t so = ((size_t)h * SQ + (kt + 1) * 64 + r) * HD + c;
                cpa16(kb +         r * AS + c, g_kh + so);
                cpa16(kb + 4608 +  r * AS + c, g_kl + so);
                cpa16(kb + 9216 +  r * AS + c, g_vh + so);
                cpa16(kb + 13824 + r * AS + c, g_vl + so);
            }
            cp_commit();
            cp_wait<1>();
        } else {
            cp_wait<0>();
        }
        __syncthreads();

        __nv_bfloat16* bKh = smb + A_KV + (size_t)buf * A_KVB;
        __nv_bfloat16* bKl = bKh + 4608;
        __nv_bfloat16* bVh = bKh + 9216;
        __nv_bfloat16* bVl = bKh + 13824;

        // ---- S = Q K^T ----
        float sfr[8][4];
#pragma unroll
        for (int nt = 0; nt < 8; nt++)
#pragma unroll
            for (int r = 0; r < 4; r++) sfr[nt][r] = 0.f;

#pragma unroll
        for (int ks = 0; ks < 4; ks++) {
            unsigned qh4[4], ql4[4];
            const int qoff = (wr + lrow) * AS + ks * 16 + lcol;
            ldsm4(qh4[0], qh4[1], qh4[2], qh4[3], sptr(sQh + qoff));
            ldsm4(ql4[0], ql4[1], ql4[2], ql4[3], sptr(sQl + qoff));
#pragma unroll
            for (int kg2 = 0; kg2 < 4; kg2++) {
                unsigned h0, h1, h2, h3, l0, l1, l2, l3;
                const int off = (kg2 * 16 + lrow) * AS + ks * 16 + lcol;
                ldsm4(h0, h1, h2, h3, sptr(bKh + off));
                ldsm4(l0, l1, l2, l3, sptr(bKl + off));
                mma16(sfr[2 * kg2], qh4, h0, h2);
                mma16(sfr[2 * kg2], qh4, l0, l2);
                mma16(sfr[2 * kg2], ql4, h0, h2);
                mma16(sfr[2 * kg2 + 1], qh4, h1, h3);
                mma16(sfr[2 * kg2 + 1], qh4, l1, l3);
                mma16(sfr[2 * kg2 + 1], ql4, h1, h3);
            }
        }

        // ---- mask + zscale + qk write + row max ----
        float rmax[2] = {-INFINITY, -INFINITY};
#pragma unroll
        for (int nt = 0; nt < 8; nt++) {
            const int c0col = nt * 8 + 2 * t;
            const float k0a = __bfloat162float(bKh[c0col * AS]);
            const float k0b = __bfloat162float(bKl[c0col * AS]);
            const float k1a = __bfloat162float(bKh[(c0col + 1) * AS]);
            const float k1b = __bfloat162float(bKl[(c0col + 1) * AS]);
            const float z0 = (k0a == 0.f && k0b == 0.f) ? zfac : 1.f;
            const float z1 = (k1a == 0.f && k1b == 0.f) ? zfac : 1.f;
#pragma unroll
            for (int half = 0; half < 2; half++) {
                const int r = q0 + wr + g + half * 8;
                float2 mk = mask2[(size_t)r * 1024 + kt * 32 + nt * 4 + t];
                float s0 = (sfr[nt][half * 2 + 0] + mk.x * z0) * z0;
                float s1 = (sfr[nt][half * 2 + 1] + mk.y * z1) * z1;
                qk2[((size_t)h * SQ + r) * 1024 + kt * 32 + nt * 4 + t] =
                    make_float2(s0, s1);
                sfr[nt][half * 2 + 0] = s0;
                sfr[nt][half * 2 + 1] = s1;
                rmax[half] = fmaxf(rmax[half], fmaxf(s0, s1));
            }
        }

        // ---- online softmax ----
        float fsc[2];
#pragma unroll
        for (int i = 0; i < 2; i++) {
            float mx = rmax[i];
            mx = fmaxf(mx, __shfl_xor_sync(0xffffffffu, mx, 1));
            mx = fmaxf(mx, __shfl_xor_sync(0xffffffffu, mx, 2));
            const float mn = fmaxf(m_i[i], mx);
            fsc[i] = __expf(m_i[i] - mn);
            m_i[i] = mn;
        }
        float psum[2] = {0.f, 0.f};
#pragma unroll
        for (int nt = 0; nt < 8; nt++)
#pragma unroll
            for (int half = 0; half < 2; half++) {
                float p0 = __expf(sfr[nt][half * 2 + 0] - m_i[half]);
                float p1 = __expf(sfr[nt][half * 2 + 1] - m_i[half]);
                sfr[nt][half * 2 + 0] = p0;
                sfr[nt][half * 2 + 1] = p1;
                psum[half] += p0 + p1;
            }
#pragma unroll
        for (int i = 0; i < 2; i++) {
            float ps = psum[i];
            ps += __shfl_xor_sync(0xffffffffu, ps, 1);
            ps += __shfl_xor_sync(0xffffffffu, ps, 2);
            l_i[i] = l_i[i] * fsc[i] + ps;
        }
#pragma unroll
        for (int nt = 0; nt < 8; nt++) {
            ofr[nt][0] *= fsc[0];
            ofr[nt][1] *= fsc[0];
            ofr[nt][2] *= fsc[1];
            ofr[nt][3] *= fsc[1];
        }

        // ---- O += P V : C-fragment of S is directly the A-fragment ----
#pragma unroll
        for (int s = 0; s < 4; s++) {
            unsigned pah[4], pal[4];
            split2(sfr[2 * s][0], sfr[2 * s][1], pah[0], pal[0]);
            split2(sfr[2 * s][2], sfr[2 * s][3], pah[1], pal[1]);
            split2(sfr[2 * s + 1][0], sfr[2 * s + 1][1], pah[2], pal[2]);
            split2(sfr[2 * s + 1][2], sfr[2 * s + 1][3], pah[3], pal[3]);
#pragma unroll
            for (int dg = 0; dg < 4; dg++) {
                unsigned h0, h1, h2, h3, l0, l1, l2, l3;
                const int off = (s * 16 + lrow) * AS + dg * 16 + lcol;
                ldsm4t(h0, h1, h2, h3, sptr(bVh + off));
                ldsm4t(l0, l1, l2, l3, sptr(bVl + off));
                mma16(ofr[2 * dg], pah, h0, h1);
                mma16(ofr[2 * dg], pah, l0, l1);
                mma16(ofr[2 * dg], pal, h0, h1);
                mma16(ofr[2 * dg + 1], pah, h2, h3);
                mma16(ofr[2 * dg + 1], pah, l2, l3);
                mma16(ofr[2 * dg + 1], pal, h2, h3);
            }
        }
        __syncthreads();
        buf ^= 1;
    }

    // ---- write wv (hi/lo split) ----
    const float inv0 = 1.f / l_i[0];
    const float inv1 = 1.f / l_i[1];
#pragma unroll
    for (int nt = 0; nt < 8; nt++) {
        const int d = h * HD + nt * 8 + 2 * t;
#pragma unroll
        for (int half = 0; half < 2; half++) {
            const int r = q0 + wr + g + half * 8;
            const float inv = half ? inv1 : inv0;
            unsigned hp, lp;
            split2(ofr[nt][half * 2 + 0] * inv, ofr[nt][half * 2 + 1] * inv, hp, lp);
            *reinterpret_cast<unsigned*>(g_oh + (size_t)r * DM + d) = hp;
            *reinterpret_cast<unsigned*>(g_ol + (size_t)r * DM + d) = lp;
        }
    }
}

// ---------------------------------------------------------------------------
extern "C" void kernel_launch(void* const* d_in, const int* in_sizes, int n_in,
                              void* d_out, int out_size)
{
    const float* x    = (const float*)d_in[0];
    const float* mask = (const float*)d_in[1];
    const float* Wq   = (const float*)d_in[2];
    const float* bq   = (const float*)d_in[3];
    const float* Wk   = (const float*)d_in[4];
    const float* Wv   = (const float*)d_in[5];
    const float* bv   = (const float*)d_in[6];
    const float* Wo   = (const float*)d_in[7];
    const float* bo   = (const float*)d_in[8];
    const float* Zf   = (const float*)d_in[9];
    const float* invf = (const float*)d_in[10];

    float* out = (float*)d_out;                       // [2048, 1024]
    float* qk  = out + (size_t)SQ * DM;               // [16, 2048, 2048]

    const int proj_smem = 2 * 4 * PBUF * 2;           // 81920 B
    const int attn_smem = (18432 + 2 * A_KVB) * 2;    // 110592 B

    static bool attrs_set = false;
    if (!attrs_set) {
        cudaFuncSetAttribute(qkv_gemm, cudaFuncAttributeMaxDynamicSharedMemorySize, proj_smem);
        cudaFuncSetAttribute(out_gemm, cudaFuncAttributeMaxDynamicSharedMemorySize, proj_smem);
        cudaFuncSetAttribute(attn_kernel, cudaFuncAttributeMaxDynamicSharedMemorySize, attn_smem);
        attrs_set = true;
    }

    rope_table<<<256, 256>>>(invf);

    // one fused launch: split x + all 4 weight matrices into hi/lo bf16
    split_all<<<dim3((SQ * DM / 4 + 255) / 256, 5), 256>>>(x, Wq, Wk, Wv, Wo);

    qkv_gemm<<<dim3(DM / 128, SQ / 128, 3), 512, proj_smem>>>(bq, bv);

    attn_kernel<<<dim3(SQ / 128, NH), 256, attn_smem>>>(mask, Zf, qk);

    out_gemm<<<dim3(DM / 128, SQ / 128), 512, proj_smem>>>(bo, out);
}

// round 13
// speedup vs baseline: 1.1483x; 1.1483x over previous
#include <cuda_runtime.h>
#include <cuda_bf16.h>
#include <math.h>

#define SQ 2048
#define DM 1024
#define NH 16
#define HD 64

// ---------------- device scratch (no allocs) ----------------
static __device__ float g_cos[SQ * 32];
static __device__ float g_sin[SQ * 32];

static __device__ __nv_bfloat16 g_xh[SQ * DM],  g_xl[SQ * DM];
static __device__ __nv_bfloat16 g_Wqh[DM * DM], g_Wql[DM * DM];
static __device__ __nv_bfloat16 g_Wkh[DM * DM], g_Wkl[DM * DM];
static __device__ __nv_bfloat16 g_Wvh[DM * DM], g_Wvl[DM * DM];
static __device__ __nv_bfloat16 g_Woh[DM * DM], g_Wol[DM * DM];
static __device__ __nv_bfloat16 g_qh[NH * SQ * HD], g_ql[NH * SQ * HD];
static __device__ __nv_bfloat16 g_kh[NH * SQ * HD], g_kl[NH * SQ * HD];
static __device__ __nv_bfloat16 g_vh[NH * SQ * HD], g_vl[NH * SQ * HD];
static __device__ __nv_bfloat16 g_oh[SQ * DM],  g_ol[SQ * DM];

// ---------------- helpers ----------------
__device__ __forceinline__ unsigned sptr(const void* p) {
    return (unsigned)__cvta_generic_to_shared(p);
}
__device__ __forceinline__ void cpa16(void* dst, const void* src) {
    asm volatile("cp.async.cg.shared.global [%0], [%1], 16;"
                 :: "r"(sptr(dst)), "l"(src));
}
__device__ __forceinline__ void cp_commit() {
    asm volatile("cp.async.commit_group;");
}
template <int N>
__device__ __forceinline__ void cp_wait() {
    asm volatile("cp.async.wait_group %0;" :: "n"(N));
}
__device__ __forceinline__ void ldsm4(unsigned& r0, unsigned& r1, unsigned& r2,
                                      unsigned& r3, unsigned a) {
    asm volatile("ldmatrix.sync.aligned.m8n8.x4.shared.b16 {%0,%1,%2,%3},[%4];"
                 : "=r"(r0), "=r"(r1), "=r"(r2), "=r"(r3) : "r"(a));
}
__device__ __forceinline__ void ldsm4t(unsigned& r0, unsigned& r1, unsigned& r2,
                                       unsigned& r3, unsigned a) {
    asm volatile("ldmatrix.sync.aligned.m8n8.x4.trans.shared.b16 {%0,%1,%2,%3},[%4];"
                 : "=r"(r0), "=r"(r1), "=r"(r2), "=r"(r3) : "r"(a));
}
__device__ __forceinline__ void mma16(float* c, const unsigned a[4],
                                      unsigned b0, unsigned b1) {
    asm volatile(
        "mma.sync.aligned.m16n8k16.row.col.f32.bf16.bf16.f32 "
        "{%0,%1,%2,%3},{%4,%5,%6,%7},{%8,%9},{%0,%1,%2,%3};"
        : "+f"(c[0]), "+f"(c[1]), "+f"(c[2]), "+f"(c[3])
        : "r"(a[0]), "r"(a[1]), "r"(a[2]), "r"(a[3]), "r"(b0), "r"(b1));
}
__device__ __forceinline__ void splitf(float x, __nv_bfloat16& h, __nv_bfloat16& l) {
    h = __float2bfloat16(x);
    l = __float2bfloat16(x - __bfloat162float(h));
}
__device__ __forceinline__ unsigned pkbf(__nv_bfloat16 a, __nv_bfloat16 b) {
    __nv_bfloat162 t = __halves2bfloat162(a, b);
    return *reinterpret_cast<unsigned*>(&t);
}
__device__ __forceinline__ void split2(float x, float y, unsigned& h, unsigned& l) {
    __nv_bfloat16 hx, lx, hy, ly;
    splitf(x, hx, lx);
    splitf(y, hy, ly);
    h = pkbf(hx, hy);
    l = pkbf(lx, ly);
}

// ---------------------------------------------------------------------------
// RoPE cos/sin table (fp64-accurate)
// ---------------------------------------------------------------------------
__global__ void rope_table(const float* __restrict__ inv_freq)
{
    const int idx = blockIdx.x * 256 + threadIdx.x;
    const int s = idx >> 5;
    const int j = idx & 31;
    const double f = (double)s * (double)inv_freq[j];
    g_cos[idx] = (float)cos(f);
    g_sin[idx] = (float)sin(f);
}

// ---------------------------------------------------------------------------
// Fused split: one launch splits x + all 4 weight matrices into hi/lo bf16.
// ---------------------------------------------------------------------------
__global__ void split_all(const float* __restrict__ x,
                          const float* __restrict__ Wq,
                          const float* __restrict__ Wk,
                          const float* __restrict__ Wv,
                          const float* __restrict__ Wo)
{
    const int which = blockIdx.y;
    const float* src;
    __nv_bfloat16* h;
    __nv_bfloat16* l;
    int n4;
    switch (which) {
        case 0: src = x;  h = g_xh;  l = g_xl;  n4 = SQ * DM / 4; break;
        case 1: src = Wq; h = g_Wqh; l = g_Wql; n4 = DM * DM / 4; break;
        case 2: src = Wk; h = g_Wkh; l = g_Wkl; n4 = DM * DM / 4; break;
        case 3: src = Wv; h = g_Wvh; l = g_Wvl; n4 = DM * DM / 4; break;
        default: src = Wo; h = g_Woh; l = g_Wol; n4 = DM * DM / 4; break;
    }
    const int i = blockIdx.x * 256 + threadIdx.x;
    if (i >= n4) return;
    float4 v = reinterpret_cast<const float4*>(src)[i];
    __nv_bfloat16 hh[4], ll[4];
    splitf(v.x, hh[0], ll[0]);
    splitf(v.y, hh[1], ll[1]);
    splitf(v.z, hh[2], ll[2]);
    splitf(v.w, hh[3], ll[3]);
    reinterpret_cast<uint2*>(h)[i] = make_uint2(pkbf(hh[0], hh[1]), pkbf(hh[2], hh[3]));
    reinterpret_cast<uint2*>(l)[i] = make_uint2(pkbf(ll[0], ll[1]), pkbf(ll[2], ll[3]));
}

// ---------------------------------------------------------------------------
// Projection GEMM core (bf16 3-term split, pre-split inputs, cp.async).
// CTA 128x128, BK=32, 512 threads = 16 warps (4m x 4n), warp tile 32x32.
// ---------------------------------------------------------------------------
#define PK 40
#define PBUF (128 * PK)

#define PJ_ISSUE(kt, b) do {                                                   \
    __nv_bfloat16* d0 = smb + (size_t)(b) * 4 * PBUF + cr * PK + cc;           \
    cpa16(d0,            Ah + (size_t)(m0 + cr) * DM + (kt) * 32 + cc);        \
    cpa16(d0 + PBUF,     Al + (size_t)(m0 + cr) * DM + (kt) * 32 + cc);        \
    cpa16(d0 + 2 * PBUF, Wh + (size_t)(n0 + cr) * DM + (kt) * 32 + cc);        \
    cpa16(d0 + 3 * PBUF, Wl + (size_t)(n0 + cr) * DM + (kt) * 32 + cc);        \
    cp_commit();                                                                \
} while (0)

__device__ __forceinline__ void proj_core(
    const __nv_bfloat16* __restrict__ Ah, const __nv_bfloat16* __restrict__ Al,
    const __nv_bfloat16* __restrict__ Wh, const __nv_bfloat16* __restrict__ Wl,
    int m0, int n0, __nv_bfloat16* smb, float acc[2][4][4], int tid)
{
    const int lane = tid & 31;
    const int wid = tid >> 5;
    const int wm = (wid & 3) * 32;
    const int wn = (wid >> 2) * 32;
    const int lrow = lane & 15;
    const int lcol = (lane >> 4) * 8;
    const int cr = tid >> 2;          // 0..127
    const int cc = (tid & 3) * 8;     // 0,8,16,24

#pragma unroll
    for (int mt = 0; mt < 2; mt++)
#pragma unroll
        for (int nt = 0; nt < 4; nt++)
#pragma unroll
            for (int r = 0; r < 4; r++) acc[mt][nt][r] = 0.f;

    PJ_ISSUE(0, 0);

    int buf = 0;
    for (int kt = 0; kt < DM / 32; kt++) {
        if (kt + 1 < DM / 32) {
            PJ_ISSUE(kt + 1, buf ^ 1);
            cp_wait<1>();
        } else {
            cp_wait<0>();
        }
        __syncthreads();

        __nv_bfloat16* sAh = smb + (size_t)buf * 4 * PBUF;
        __nv_bfloat16* sAl = sAh + PBUF;
        __nv_bfloat16* sWh = sAh + 2 * PBUF;
        __nv_bfloat16* sWl = sAh + 3 * PBUF;

#pragma unroll
        for (int ks = 0; ks < 2; ks++) {
            unsigned ah[2][4], al[2][4];
#pragma unroll
            for (int mt = 0; mt < 2; mt++) {
                const int off = (wm + mt * 16 + lrow) * PK + ks * 16 + lcol;
                ldsm4(ah[mt][0], ah[mt][1], ah[mt][2], ah[mt][3], sptr(sAh + off));
                ldsm4(al[mt][0], al[mt][1], al[mt][2], al[mt][3], sptr(sAl + off));
            }
#pragma unroll
            for (int ng = 0; ng < 2; ng++) {
                unsigned h0, h1, h2, h3, l0, l1, l2, l3;
                const int off = (wn + ng * 16 + lrow) * PK + ks * 16 + lcol;
                ldsm4(h0, h1, h2, h3, sptr(sWh + off));
                ldsm4(l0, l1, l2, l3, sptr(sWl + off));
#pragma unroll
                for (int mt = 0; mt < 2; mt++) {
                    mma16(acc[mt][2 * ng], ah[mt], h0, h2);
                    mma16(acc[mt][2 * ng], ah[mt], l0, l2);
                    mma16(acc[mt][2 * ng], al[mt], h0, h2);
                    mma16(acc[mt][2 * ng + 1], ah[mt], h1, h3);
                    mma16(acc[mt][2 * ng + 1], ah[mt], l1, l3);
                    mma16(acc[mt][2 * ng + 1], al[mt], h1, h3);
                }
            }
        }
        __syncthreads();
        buf ^= 1;
    }
}

// ---------------------------------------------------------------------------
// Fused QKV GEMM + bias + RoPE + scale; outputs hi/lo bf16 head-layout arrays.
// ---------------------------------------------------------------------------
__global__ void __launch_bounds__(512) qkv_gemm(
    const float* __restrict__ bq, const float* __restrict__ bv)
{
    extern __shared__ __align__(16) __nv_bfloat16 smb[];
    const int tid = threadIdx.x;
    const int z = blockIdx.z;
    const int m0 = blockIdx.y * 128;
    const int n0 = blockIdx.x * 128;

    const __nv_bfloat16* Wh = (z == 0) ? g_Wqh : (z == 1) ? g_Wkh : g_Wvh;
    const __nv_bfloat16* Wl = (z == 0) ? g_Wql : (z == 1) ? g_Wkl : g_Wvl;
    const float* bias = (z == 0) ? bq : (z == 2) ? bv : nullptr;
    __nv_bfloat16* outh = (z == 0) ? g_qh : (z == 1) ? g_kh : g_vh;
    __nv_bfloat16* outl = (z == 0) ? g_ql : (z == 1) ? g_kl : g_vl;

    float acc[2][4][4];
    proj_core(g_xh, g_xl, Wh, Wl, m0, n0, smb, acc, tid);

    const int lane = tid & 31;
    const int wid = tid >> 5;
    const int g = lane >> 2;
    const int t = lane & 3;
    const int wm = (wid & 3) * 32;
    const int wn = (wid >> 2) * 32;
    const float rsc = 0.35355339059327373f;   // 64^(-1/4)

#pragma unroll
    for (int mt = 0; mt < 2; mt++) {
#pragma unroll
        for (int nt = 0; nt < 4; nt++) {
            const int n = n0 + wn + nt * 8 + 2 * t;
            const int hh = n >> 6;
            const int d = n & 63;
            const float b0v = bias ? bias[n] : 0.f;
            const float b1v = bias ? bias[n + 1] : 0.f;
#pragma unroll
            for (int half = 0; half < 2; half++) {
                const int m = m0 + wm + mt * 16 + g + half * 8;
                float a = acc[mt][nt][half * 2 + 0] + b0v;
                float b = acc[mt][nt][half * 2 + 1] + b1v;
                const size_t off = ((size_t)hh * SQ + m) * HD + d;
                unsigned hp, lp;
                if (z < 2) {
                    const int pi = d >> 1;
                    const float c = g_cos[m * 32 + pi];
                    const float s = g_sin[m * 32 + pi];
                    split2(rsc * (a * c - b * s), rsc * (a * s + b * c), hp, lp);
                } else {
                    split2(a, b, hp, lp);
                }
                *reinterpret_cast<unsigned*>(outh + off) = hp;
                *reinterpret_cast<unsigned*>(outl + off) = lp;
            }
        }
    }
}

// ---------------------------------------------------------------------------
// Output projection: out = wv(split) @ Wo^T + bo, fp32 row-major
// ---------------------------------------------------------------------------
__global__ void __launch_bounds__(512) out_gemm(
    const float* __restrict__ bo, float* __restrict__ C)
{
    extern __shared__ __align__(16) __nv_bfloat16 smb[];
    const int tid = threadIdx.x;
    const int m0 = blockIdx.y * 128;
    const int n0 = blockIdx.x * 128;

    float acc[2][4][4];
    proj_core(g_oh, g_ol, g_Woh, g_Wol, m0, n0, smb, acc, tid);

    const int lane = tid & 31;
    const int wid = tid >> 5;
    const int g = lane >> 2;
    const int t = lane & 3;
    const int wm = (wid & 3) * 32;
    const int wn = (wid >> 2) * 32;

#pragma unroll
    for (int mt = 0; mt < 2; mt++) {
#pragma unroll
        for (int nt = 0; nt < 4; nt++) {
            const int n = n0 + wn + nt * 8 + 2 * t;
            const float b0v = bo[n], b1v = bo[n + 1];
#pragma unroll
            for (int half = 0; half < 2; half++) {
                const int m = m0 + wm + mt * 16 + g + half * 8;
                *reinterpret_cast<float2*>(C + (size_t)m * DM + n) =
                    make_float2(acc[mt][nt][half * 2 + 0] + b0v,
                                acc[mt][nt][half * 2 + 1] + b1v);
            }
        }
    }
}

// ---------------------------------------------------------------------------
// Attention. CTA: 1 head x 128 q rows, 256 threads = 8 warps x 16 rows.
// grid = 256 CTAs. Register cap via __maxnreg__(128) ONLY (no launch_bounds;
// nvcc forbids combining them, and launch_bounds minBlocks correlates with
// container failures). 2 CTAs/SM: 2x256x128 = 64K regs, 2x110.6 KB smem.
// ---------------------------------------------------------------------------
#define AS 72
#define A_QH 0
#define A_QL 9216
#define A_KV 18432
#define A_KVB 18432

__global__ void __maxnreg__(128) attn_kernel(
    const float* __restrict__ mask, const float* __restrict__ Zf,
    float* __restrict__ qk_out)
{
    extern __shared__ __align__(16) __nv_bfloat16 smb[];
    __nv_bfloat16* sQh = smb + A_QH;
    __nv_bfloat16* sQl = smb + A_QL;

    const int tid = threadIdx.x;
    const int lane = tid & 31;
    const int wid = tid >> 5;
    const int g = lane >> 2;
    const int t = lane & 3;
    const int lrow = lane & 15;
    const int lcol = (lane >> 4) * 8;
    const int wr = wid * 16;
    const int h = blockIdx.y;
    const int q0 = blockIdx.x * 128;

    const float zfac = fminf(fmaxf(log1pf(expf(Zf[0])), 1e-5f), 1e-4f);

    // ---- prologue: Q copy (128 rows) + KV tile 0 ----
#pragma unroll
    for (int i = 0; i < 4; i++) {
        const int idx = tid + i * 256;           // 0..1023
        const int r = idx >> 3;
        const int c = (idx & 7) * 8;
        const size_t so = ((size_t)h * SQ + q0 + r) * HD + c;
        cpa16(sQh + r * AS + c, g_qh + so);
        cpa16(sQl + r * AS + c, g_ql + so);
    }
    {
        __nv_bfloat16* kb = smb + A_KV;
#pragma unroll
        for (int i = 0; i < 2; i++) {
            const int idx = tid + i * 256;        // 0..511
            const int r = idx >> 3;
            const int c = (idx & 7) * 8;
            const size_t so = ((size_t)h * SQ + r) * HD + c;
            cpa16(kb +         r * AS + c, g_kh + so);
            cpa16(kb + 4608 +  r * AS + c, g_kl + so);
            cpa16(kb + 9216 +  r * AS + c, g_vh + so);
            cpa16(kb + 13824 + r * AS + c, g_vl + so);
        }
        cp_commit();
    }

    float ofr[8][4];
    float m_i[2], l_i[2];
#pragma unroll
    for (int nt = 0; nt < 8; nt++)
#pragma unroll
        for (int r = 0; r < 4; r++) ofr[nt][r] = 0.f;
    m_i[0] = m_i[1] = -INFINITY;
    l_i[0] = l_i[1] = 0.f;

    const float2* mask2 = reinterpret_cast<const float2*>(mask);
    float2* qk2 = reinterpret_cast<float2*>(qk_out);

    int buf = 0;
    for (int kt = 0; kt < SQ / 64; kt++) {
        if (kt + 1 < SQ / 64) {
            __nv_bfloat16* kb = smb + A_KV + (size_t)(buf ^ 1) * A_KVB;
#pragma unroll
            for (int i = 0; i < 2; i++) {
                const int idx = tid + i * 256;
                const int r = idx >> 3;
                const int c = (idx & 7) * 8;
                const size_t so = ((size_t)h * SQ + (kt + 1) * 64 + r) * HD + c;
                cpa16(kb +         r * AS + c, g_kh + so);
                cpa16(kb + 4608 +  r * AS + c, g_kl + so);
                cpa16(kb + 9216 +  r * AS + c, g_vh + so);
                cpa16(kb + 13824 + r * AS + c, g_vl + so);
            }
            cp_commit();
            cp_wait<1>();
        } else {
            cp_wait<0>();
        }
        __syncthreads();

        __nv_bfloat16* bKh = smb + A_KV + (size_t)buf * A_KVB;
        __nv_bfloat16* bKl = bKh + 4608;
        __nv_bfloat16* bVh = bKh + 9216;
        __nv_bfloat16* bVl = bKh + 13824;

        // ---- S = Q K^T ----
        float sfr[8][4];
#pragma unroll
        for (int nt = 0; nt < 8; nt++)
#pragma unroll
            for (int r = 0; r < 4; r++) sfr[nt][r] = 0.f;

#pragma unroll
        for (int ks = 0; ks < 4; ks++) {
            unsigned qh4[4], ql4[4];
            const int qoff = (wr + lrow) * AS + ks * 16 + lcol;
            ldsm4(qh4[0], qh4[1], qh4[2], qh4[3], sptr(sQh + qoff));
            ldsm4(ql4[0], ql4[1], ql4[2], ql4[3], sptr(sQl + qoff));
#pragma unroll
            for (int kg2 = 0; kg2 < 4; kg2++) {
                unsigned h0, h1, h2, h3, l0, l1, l2, l3;
                const int off = (kg2 * 16 + lrow) * AS + ks * 16 + lcol;
                ldsm4(h0, h1, h2, h3, sptr(bKh + off));
                ldsm4(l0, l1, l2, l3, sptr(bKl + off));
                mma16(sfr[2 * kg2], qh4, h0, h2);
                mma16(sfr[2 * kg2], qh4, l0, l2);
                mma16(sfr[2 * kg2], ql4, h0, h2);
                mma16(sfr[2 * kg2 + 1], qh4, h1, h3);
                mma16(sfr[2 * kg2 + 1], qh4, l1, l3);
                mma16(sfr[2 * kg2 + 1], ql4, h1, h3);
            }
        }

        // ---- mask + zscale + qk write + row max ----
        float rmax[2] = {-INFINITY, -INFINITY};
#pragma unroll
        for (int nt = 0; nt < 8; nt++) {
            const int c0col = nt * 8 + 2 * t;
            const float k0a = __bfloat162float(bKh[c0col * AS]);
            const float k0b = __bfloat162float(bKl[c0col * AS]);
            const float k1a = __bfloat162float(bKh[(c0col + 1) * AS]);
            const float k1b = __bfloat162float(bKl[(c0col + 1) * AS]);
            const float z0 = (k0a == 0.f && k0b == 0.f) ? zfac : 1.f;
            const float z1 = (k1a == 0.f && k1b == 0.f) ? zfac : 1.f;
#pragma unroll
            for (int half = 0; half < 2; half++) {
                const int r = q0 + wr + g + half * 8;
                float2 mk = mask2[(size_t)r * 1024 + kt * 32 + nt * 4 + t];
                float s0 = (sfr[nt][half * 2 + 0] + mk.x * z0) * z0;
                float s1 = (sfr[nt][half * 2 + 1] + mk.y * z1) * z1;
                qk2[((size_t)h * SQ + r) * 1024 + kt * 32 + nt * 4 + t] =
                    make_float2(s0, s1);
                sfr[nt][half * 2 + 0] = s0;
                sfr[nt][half * 2 + 1] = s1;
                rmax[half] = fmaxf(rmax[half], fmaxf(s0, s1));
            }
        }

        // ---- online softmax ----
        float fsc[2];
#pragma unroll
        for (int i = 0; i < 2; i++) {
            float mx = rmax[i];
            mx = fmaxf(mx, __shfl_xor_sync(0xffffffffu, mx, 1));
            mx = fmaxf(mx, __shfl_xor_sync(0xffffffffu, mx, 2));
            const float mn = fmaxf(m_i[i], mx);
            fsc[i] = __expf(m_i[i] - mn);
            m_i[i] = mn;
        }
        float psum[2] = {0.f, 0.f};
#pragma unroll
        for (int nt = 0; nt < 8; nt++)
#pragma unroll
            for (int half = 0; half < 2; half++) {
                float p0 = __expf(sfr[nt][half * 2 + 0] - m_i[half]);
                float p1 = __expf(sfr[nt][half * 2 + 1] - m_i[half]);
                sfr[nt][half * 2 + 0] = p0;
                sfr[nt][half * 2 + 1] = p1;
                psum[half] += p0 + p1;
            }
#pragma unroll
        for (int i = 0; i < 2; i++) {
            float ps = psum[i];
            ps += __shfl_xor_sync(0xffffffffu, ps, 1);
            ps += __shfl_xor_sync(0xffffffffu, ps, 2);
            l_i[i] = l_i[i] * fsc[i] + ps;
        }
#pragma unroll
        for (int nt = 0; nt < 8; nt++) {
            ofr[nt][0] *= fsc[0];
            ofr[nt][1] *= fsc[0];
            ofr[nt][2] *= fsc[1];
            ofr[nt][3] *= fsc[1];
        }

        // ---- O += P V : C-fragment of S is directly the A-fragment ----
#pragma unroll
        for (int s = 0; s < 4; s++) {
            unsigned pah[4], pal[4];
            split2(sfr[2 * s][0], sfr[2 * s][1], pah[0], pal[0]);
            split2(sfr[2 * s][2], sfr[2 * s][3], pah[1], pal[1]);
            split2(sfr[2 * s + 1][0], sfr[2 * s + 1][1], pah[2], pal[2]);
            split2(sfr[2 * s + 1][2], sfr[2 * s + 1][3], pah[3], pal[3]);
#pragma unroll
            for (int dg = 0; dg < 4; dg++) {
                unsigned h0, h1, h2, h3, l0, l1, l2, l3;
                const int off = (s * 16 + lrow) * AS + dg * 16 + lcol;
                ldsm4t(h0, h1, h2, h3, sptr(bVh + off));
                ldsm4t(l0, l1, l2, l3, sptr(bVl + off));
                mma16(ofr[2 * dg], pah, h0, h1);
                mma16(ofr[2 * dg], pah, l0, l1);
                mma16(ofr[2 * dg], pal, h0, h1);
                mma16(ofr[2 * dg + 1], pah, h2, h3);
                mma16(ofr[2 * dg + 1], pah, l2, l3);
                mma16(ofr[2 * dg + 1], pal, h2, h3);
            }
        }
        __syncthreads();
        buf ^= 1;
    }

    // ---- write wv (hi/lo split) ----
    const float inv0 = 1.f / l_i[0];
    const float inv1 = 1.f / l_i[1];
#pragma unroll
    for (int nt = 0; nt < 8; nt++) {
        const int d = h * HD + nt * 8 + 2 * t;
#pragma unroll
        for (int half = 0; half < 2; half++) {
            const int r = q0 + wr + g + half * 8;
            const float inv = half ? inv1 : inv0;
            unsigned hp, lp;
            split2(ofr[nt][half * 2 + 0] * inv, ofr[nt][half * 2 + 1] * inv, hp, lp);
            *reinterpret_cast<unsigned*>(g_oh + (size_t)r * DM + d) = hp;
            *reinterpret_cast<unsigned*>(g_ol + (size_t)r * DM + d) = lp;
        }
    }
}

// ---------------------------------------------------------------------------
extern "C" void kernel_launch(void* const* d_in, const int* in_sizes, int n_in,
                              void* d_out, int out_size)
{
    const float* x    = (const float*)d_in[0];
    const float* mask = (const float*)d_in[1];
    const float* Wq   = (const float*)d_in[2];
    const float* bq   = (const float*)d_in[3];
    const float* Wk   = (const float*)d_in[4];
    const float* Wv   = (const float*)d_in[5];
    const float* bv   = (const float*)d_in[6];
    const float* Wo   = (const float*)d_in[7];
    const float* bo   = (const float*)d_in[8];
    const float* Zf   = (const float*)d_in[9];
    const float* invf = (const float*)d_in[10];

    float* out = (float*)d_out;                       // [2048, 1024]
    float* qk  = out + (size_t)SQ * DM;               // [16, 2048, 2048]

    const int proj_smem = 2 * 4 * PBUF * 2;           // 81920 B
    const int attn_smem = (18432 + 2 * A_KVB) * 2;    // 110592 B

    static bool attrs_set = false;
    if (!attrs_set) {
        cudaFuncSetAttribute(qkv_gemm, cudaFuncAttributeMaxDynamicSharedMemorySize, proj_smem);
        cudaFuncSetAttribute(out_gemm, cudaFuncAttributeMaxDynamicSharedMemorySize, proj_smem);
        cudaFuncSetAttribute(attn_kernel, cudaFuncAttributeMaxDynamicSharedMemorySize, attn_smem);
        attrs_set = true;
    }

    rope_table<<<256, 256>>>(invf);

    // one fused launch: split x + all 4 weight matrices into hi/lo bf16
    split_all<<<dim3((SQ * DM / 4 + 255) / 256, 5), 256>>>(x, Wq, Wk, Wv, Wo);

    qkv_gemm<<<dim3(DM / 128, SQ / 128, 3), 512, proj_smem>>>(bq, bv);

    attn_kernel<<<dim3(SQ / 128, NH), 256, attn_smem>>>(mask, Zf, qk);

    out_gemm<<<dim3(DM / 128, SQ / 128), 512, proj_smem>>>(bo, out);
}

// round 14
// speedup vs baseline: 1.4879x; 1.2957x over previous
#include <cuda_runtime.h>
#include <cuda_fp16.h>
#include <math.h>

#define SQ 2048
#define DM 1024
#define NH 16
#define HD 64

// ---------------- device scratch (no allocs) ----------------
static __device__ float g_cos[SQ * 32];
static __device__ float g_sin[SQ * 32];

static __device__ __half g_xh[SQ * DM];                    // A-side: hi only
static __device__ __half g_Wqh[DM * DM], g_Wql[DM * DM];   // B-side: hi+lo
static __device__ __half g_Wkh[DM * DM], g_Wkl[DM * DM];
static __device__ __half g_Wvh[DM * DM], g_Wvl[DM * DM];
static __device__ __half g_Woh[DM * DM], g_Wol[DM * DM];
static __device__ __half g_qh[NH * SQ * HD];               // Q: A-side, hi only
static __device__ __half g_kh[NH * SQ * HD], g_kl[NH * SQ * HD];
static __device__ __half g_vh[NH * SQ * HD], g_vl[NH * SQ * HD];
static __device__ __half g_oh[SQ * DM];                    // wv: A-side, hi only

// ---------------- helpers ----------------
__device__ __forceinline__ unsigned sptr(const void* p) {
    return (unsigned)__cvta_generic_to_shared(p);
}
__device__ __forceinline__ void cpa16(void* dst, const void* src) {
    asm volatile("cp.async.cg.shared.global [%0], [%1], 16;"
                 :: "r"(sptr(dst)), "l"(src));
}
__device__ __forceinline__ void cp_commit() {
    asm volatile("cp.async.commit_group;");
}
template <int N>
__device__ __forceinline__ void cp_wait() {
    asm volatile("cp.async.wait_group %0;" :: "n"(N));
}
__device__ __forceinline__ void ldsm4(unsigned& r0, unsigned& r1, unsigned& r2,
                                      unsigned& r3, unsigned a) {
    asm volatile("ldmatrix.sync.aligned.m8n8.x4.shared.b16 {%0,%1,%2,%3},[%4];"
                 : "=r"(r0), "=r"(r1), "=r"(r2), "=r"(r3) : "r"(a));
}
__device__ __forceinline__ void ldsm4t(unsigned& r0, unsigned& r1, unsigned& r2,
                                       unsigned& r3, unsigned a) {
    asm volatile("ldmatrix.sync.aligned.m8n8.x4.trans.shared.b16 {%0,%1,%2,%3},[%4];"
                 : "=r"(r0), "=r"(r1), "=r"(r2), "=r"(r3) : "r"(a));
}
__device__ __forceinline__ void mmah(float* c, const unsigned a[4],
                                     unsigned b0, unsigned b1) {
    asm volatile(
        "mma.sync.aligned.m16n8k16.row.col.f32.f16.f16.f32 "
        "{%0,%1,%2,%3},{%4,%5,%6,%7},{%8,%9},{%0,%1,%2,%3};"
        : "+f"(c[0]), "+f"(c[1]), "+f"(c[2]), "+f"(c[3])
        : "r"(a[0]), "r"(a[1]), "r"(a[2]), "r"(a[3]), "r"(b0), "r"(b1));
}
__device__ __forceinline__ void splith(float x, __half& h, __half& l) {
    h = __float2half_rn(x);
    l = __float2half_rn(x - __half2float(h));
}
__device__ __forceinline__ unsigned pkh(__half a, __half b) {
    __half2 t = __halves2half2(a, b);
    return *reinterpret_cast<unsigned*>(&t);
}
__device__ __forceinline__ unsigned cvt2h(float x, float y) {
    __half2 t = __floats2half2_rn(x, y);
    return *reinterpret_cast<unsigned*>(&t);
}
__device__ __forceinline__ void split2h(float x, float y, unsigned& h, unsigned& l) {
    __half hx, lx, hy, ly;
    splith(x, hx, lx);
    splith(y, hy, ly);
    h = pkh(hx, hy);
    l = pkh(lx, ly);
}

// ---------------------------------------------------------------------------
// RoPE cos/sin table (fp64-accurate)
// ---------------------------------------------------------------------------
__global__ void rope_table(const float* __restrict__ inv_freq)
{
    const int idx = blockIdx.x * 256 + threadIdx.x;
    const int s = idx >> 5;
    const int j = idx & 31;
    const double f = (double)s * (double)inv_freq[j];
    g_cos[idx] = (float)cos(f);
    g_sin[idx] = (float)sin(f);
}

// ---------------------------------------------------------------------------
// Fused split: x -> hi only; weights -> hi+lo. blockIdx.y selects target.
// ---------------------------------------------------------------------------
__global__ void split_all(const float* __restrict__ x,
                          const float* __restrict__ Wq,
                          const float* __restrict__ Wk,
                          const float* __restrict__ Wv,
                          const float* __restrict__ Wo)
{
    const int which = blockIdx.y;
    const float* src;
    __half* h;
    __half* l;
    int n4;
    switch (which) {
        case 0: src = x;  h = g_xh;  l = nullptr; n4 = SQ * DM / 4; break;
        case 1: src = Wq; h = g_Wqh; l = g_Wql;   n4 = DM * DM / 4; break;
        case 2: src = Wk; h = g_Wkh; l = g_Wkl;   n4 = DM * DM / 4; break;
        case 3: src = Wv; h = g_Wvh; l = g_Wvl;   n4 = DM * DM / 4; break;
        default: src = Wo; h = g_Woh; l = g_Wol;  n4 = DM * DM / 4; break;
    }
    const int i = blockIdx.x * 256 + threadIdx.x;
    if (i >= n4) return;
    float4 v = reinterpret_cast<const float4*>(src)[i];
    __half hh[4], ll[4];
    splith(v.x, hh[0], ll[0]);
    splith(v.y, hh[1], ll[1]);
    splith(v.z, hh[2], ll[2]);
    splith(v.w, hh[3], ll[3]);
    reinterpret_cast<uint2*>(h)[i] = make_uint2(pkh(hh[0], hh[1]), pkh(hh[2], hh[3]));
    if (l)
        reinterpret_cast<uint2*>(l)[i] = make_uint2(pkh(ll[0], ll[1]), pkh(ll[2], ll[3]));
}

// ---------------------------------------------------------------------------
// Projection GEMM core (fp16 2-term: C = Ah*Wh^T + Ah*Wl^T), cp.async.
// CTA 128x128, BK=32, 512 threads = 16 warps (4m x 4n), warp tile 32x32.
// smem per buffer: 3 matrices [128][PK] half (Ah, Wh, Wl), double buffered.
// ---------------------------------------------------------------------------
#define PK 40
#define PBUF (128 * PK)

#define PJ_ISSUE(kt, b) do {                                                   \
    __half* d0 = smb + (size_t)(b) * 3 * PBUF + cr * PK + cc;                  \
    cpa16(d0,            Ah + (size_t)(m0 + cr) * DM + (kt) * 32 + cc);        \
    cpa16(d0 + PBUF,     Wh + (size_t)(n0 + cr) * DM + (kt) * 32 + cc);        \
    cpa16(d0 + 2 * PBUF, Wl + (size_t)(n0 + cr) * DM + (kt) * 32 + cc);        \
    cp_commit();                                                                \
} while (0)

__device__ __forceinline__ void proj_core(
    const __half* __restrict__ Ah,
    const __half* __restrict__ Wh, const __half* __restrict__ Wl,
    int m0, int n0, __half* smb, float acc[2][4][4], int tid)
{
    const int lane = tid & 31;
    const int wid = tid >> 5;
    const int wm = (wid & 3) * 32;
    const int wn = (wid >> 2) * 32;
    const int lrow = lane & 15;
    const int lcol = (lane >> 4) * 8;
    const int cr = tid >> 2;          // 0..127
    const int cc = (tid & 3) * 8;     // 0,8,16,24

#pragma unroll
    for (int mt = 0; mt < 2; mt++)
#pragma unroll
        for (int nt = 0; nt < 4; nt++)
#pragma unroll
            for (int r = 0; r < 4; r++) acc[mt][nt][r] = 0.f;

    PJ_ISSUE(0, 0);

    int buf = 0;
    for (int kt = 0; kt < DM / 32; kt++) {
        if (kt + 1 < DM / 32) {
            PJ_ISSUE(kt + 1, buf ^ 1);
            cp_wait<1>();
        } else {
            cp_wait<0>();
        }
        __syncthreads();

        __half* sAh = smb + (size_t)buf * 3 * PBUF;
        __half* sWh = sAh + PBUF;
        __half* sWl = sAh + 2 * PBUF;

#pragma unroll
        for (int ks = 0; ks < 2; ks++) {
            unsigned ah[2][4];
#pragma unroll
            for (int mt = 0; mt < 2; mt++) {
                const int off = (wm + mt * 16 + lrow) * PK + ks * 16 + lcol;
                ldsm4(ah[mt][0], ah[mt][1], ah[mt][2], ah[mt][3], sptr(sAh + off));
            }
#pragma unroll
            for (int ng = 0; ng < 2; ng++) {
                unsigned h0, h1, h2, h3, l0, l1, l2, l3;
                const int off = (wn + ng * 16 + lrow) * PK + ks * 16 + lcol;
                ldsm4(h0, h1, h2, h3, sptr(sWh + off));
                ldsm4(l0, l1, l2, l3, sptr(sWl + off));
#pragma unroll
                for (int mt = 0; mt < 2; mt++) {
                    mmah(acc[mt][2 * ng], ah[mt], h0, h2);
                    mmah(acc[mt][2 * ng], ah[mt], l0, l2);
                    mmah(acc[mt][2 * ng + 1], ah[mt], h1, h3);
                    mmah(acc[mt][2 * ng + 1], ah[mt], l1, l3);
                }
            }
        }
        __syncthreads();
        buf ^= 1;
    }
}

// ---------------------------------------------------------------------------
// Fused QKV GEMM + bias + RoPE + scale; q -> hi only, k/v -> hi+lo.
// ---------------------------------------------------------------------------
__global__ void __launch_bounds__(512) qkv_gemm(
    const float* __restrict__ bq, const float* __restrict__ bv)
{
    extern __shared__ __align__(16) __half smb[];
    const int tid = threadIdx.x;
    const int z = blockIdx.z;
    const int m0 = blockIdx.y * 128;
    const int n0 = blockIdx.x * 128;

    const __half* Wh = (z == 0) ? g_Wqh : (z == 1) ? g_Wkh : g_Wvh;
    const __half* Wl = (z == 0) ? g_Wql : (z == 1) ? g_Wkl : g_Wvl;
    const float* bias = (z == 0) ? bq : (z == 2) ? bv : nullptr;
    __half* outh = (z == 0) ? g_qh : (z == 1) ? g_kh : g_vh;
    __half* outl = (z == 1) ? g_kl : g_vl;   // unused for z==0

    float acc[2][4][4];
    proj_core(g_xh, Wh, Wl, m0, n0, smb, acc, tid);

    const int lane = tid & 31;
    const int wid = tid >> 5;
    const int g = lane >> 2;
    const int t = lane & 3;
    const int wm = (wid & 3) * 32;
    const int wn = (wid >> 2) * 32;
    const float rsc = 0.35355339059327373f;   // 64^(-1/4)

#pragma unroll
    for (int mt = 0; mt < 2; mt++) {
#pragma unroll
        for (int nt = 0; nt < 4; nt++) {
            const int n = n0 + wn + nt * 8 + 2 * t;
            const int hh = n >> 6;
            const int d = n & 63;
            const float b0v = bias ? bias[n] : 0.f;
            const float b1v = bias ? bias[n + 1] : 0.f;
#pragma unroll
            for (int half = 0; half < 2; half++) {
                const int m = m0 + wm + mt * 16 + g + half * 8;
                float a = acc[mt][nt][half * 2 + 0] + b0v;
                float b = acc[mt][nt][half * 2 + 1] + b1v;
                const size_t off = ((size_t)hh * SQ + m) * HD + d;
                if (z < 2) {
                    const int pi = d >> 1;
                    const float c = g_cos[m * 32 + pi];
                    const float s = g_sin[m * 32 + pi];
                    const float ra = rsc * (a * c - b * s);
                    const float rb = rsc * (a * s + b * c);
                    if (z == 0) {
                        *reinterpret_cast<unsigned*>(outh + off) = cvt2h(ra, rb);
                    } else {
                        unsigned hp, lp;
                        split2h(ra, rb, hp, lp);
                        *reinterpret_cast<unsigned*>(outh + off) = hp;
                        *reinterpret_cast<unsigned*>(outl + off) = lp;
                    }
                } else {
                    unsigned hp, lp;
                    split2h(a, b, hp, lp);
                    *reinterpret_cast<unsigned*>(outh + off) = hp;
                    *reinterpret_cast<unsigned*>(outl + off) = lp;
                }
            }
        }
    }
}

// ---------------------------------------------------------------------------
// Output projection: out = wv(hi) @ Wo(hi+lo)^T + bo, fp32 row-major
// ---------------------------------------------------------------------------
__global__ void __launch_bounds__(512) out_gemm(
    const float* __restrict__ bo, float* __restrict__ C)
{
    extern __shared__ __align__(16) __half smb[];
    const int tid = threadIdx.x;
    const int m0 = blockIdx.y * 128;
    const int n0 = blockIdx.x * 128;

    float acc[2][4][4];
    proj_core(g_oh, g_Woh, g_Wol, m0, n0, smb, acc, tid);

    const int lane = tid & 31;
    const int wid = tid >> 5;
    const int g = lane >> 2;
    const int t = lane & 3;
    const int wm = (wid & 3) * 32;
    const int wn = (wid >> 2) * 32;

#pragma unroll
    for (int mt = 0; mt < 2; mt++) {
#pragma unroll
        for (int nt = 0; nt < 4; nt++) {
            const int n = n0 + wn + nt * 8 + 2 * t;
            const float b0v = bo[n], b1v = bo[n + 1];
#pragma unroll
            for (int half = 0; half < 2; half++) {
                const int m = m0 + wm + mt * 16 + g + half * 8;
                *reinterpret_cast<float2*>(C + (size_t)m * DM + n) =
                    make_float2(acc[mt][nt][half * 2 + 0] + b0v,
                                acc[mt][nt][half * 2 + 1] + b1v);
            }
        }
    }
}

// ---------------------------------------------------------------------------
// Attention. CTA: 1 head x 128 q rows, 256 threads = 8 warps x 16 rows.
// fp16 2-term: S = Qh*(Kh+Kl)^T, O += Ph*(Vh+Vl). Q hi-only in smem.
// smem halfs: sQh[128*72] + 2 x {Kh,Kl,Vh,Vl}[64*72] = 46080 (92 KB).
// __maxnreg__(128) -> 2 CTAs/SM (64K regs, 184 KB smem).
// ---------------------------------------------------------------------------
#define AS 72
#define A_QH 0
#define A_KV 9216
#define A_KVB 18432

__global__ void __maxnreg__(128) attn_kernel(
    const float* __restrict__ mask, const float* __restrict__ Zf,
    float* __restrict__ qk_out)
{
    extern __shared__ __align__(16) __half smb[];
    __half* sQh = smb + A_QH;

    const int tid = threadIdx.x;
    const int lane = tid & 31;
    const int wid = tid >> 5;
    const int g = lane >> 2;
    const int t = lane & 3;
    const int lrow = lane & 15;
    const int lcol = (lane >> 4) * 8;
    const int wr = wid * 16;
    const int h = blockIdx.y;
    const int q0 = blockIdx.x * 128;

    const float zfac = fminf(fmaxf(log1pf(expf(Zf[0])), 1e-5f), 1e-4f);

    // ---- prologue: Q copy (hi only) + KV tile 0 ----
#pragma unroll
    for (int i = 0; i < 4; i++) {
        const int idx = tid + i * 256;           // 0..1023
        const int r = idx >> 3;
        const int c = (idx & 7) * 8;
        cpa16(sQh + r * AS + c, g_qh + ((size_t)h * SQ + q0 + r) * HD + c);
    }
    {
        __half* kb = smb + A_KV;
#pragma unroll
        for (int i = 0; i < 2; i++) {
            const int idx = tid + i * 256;        // 0..511
            const int r = idx >> 3;
            const int c = (idx & 7) * 8;
            const size_t so = ((size_t)h * SQ + r) * HD + c;
            cpa16(kb +         r * AS + c, g_kh + so);
            cpa16(kb + 4608 +  r * AS + c, g_kl + so);
            cpa16(kb + 9216 +  r * AS + c, g_vh + so);
            cpa16(kb + 13824 + r * AS + c, g_vl + so);
        }
        cp_commit();
    }

    float ofr[8][4];
    float m_i[2], l_i[2];
#pragma unroll
    for (int nt = 0; nt < 8; nt++)
#pragma unroll
        for (int r = 0; r < 4; r++) ofr[nt][r] = 0.f;
    m_i[0] = m_i[1] = -INFINITY;
    l_i[0] = l_i[1] = 0.f;

    const float2* mask2 = reinterpret_cast<const float2*>(mask);
    float2* qk2 = reinterpret_cast<float2*>(qk_out);

    int buf = 0;
    for (int kt = 0; kt < SQ / 64; kt++) {
        if (kt + 1 < SQ / 64) {
            __half* kb = smb + A_KV + (size_t)(buf ^ 1) * A_KVB;
#pragma unroll
            for (int i = 0; i < 2; i++) {
                const int idx = tid + i * 256;
                const int r = idx >> 3;
                const int c = (idx & 7) * 8;
                const size_t so = ((size_t)h * SQ + (kt + 1) * 64 + r) * HD + c;
                cpa16(kb +         r * AS + c, g_kh + so);
                cpa16(kb + 4608 +  r * AS + c, g_kl + so);
                cpa16(kb + 9216 +  r * AS + c, g_vh + so);
                cpa16(kb + 13824 + r * AS + c, g_vl + so);
            }
            cp_commit();
            cp_wait<1>();
        } else {
            cp_wait<0>();
        }
        __syncthreads();

        __half* bKh = smb + A_KV + (size_t)buf * A_KVB;
        __half* bKl = bKh + 4608;
        __half* bVh = bKh + 9216;
        __half* bVl = bKh + 13824;

        // ---- S = Qh (Kh + Kl)^T ----
        float sfr[8][4];
#pragma unroll
        for (int nt = 0; nt < 8; nt++)
#pragma unroll
            for (int r = 0; r < 4; r++) sfr[nt][r] = 0.f;

#pragma unroll
        for (int ks = 0; ks < 4; ks++) {
            unsigned qh4[4];
            ldsm4(qh4[0], qh4[1], qh4[2], qh4[3],
                  sptr(sQh + (wr + lrow) * AS + ks * 16 + lcol));
#pragma unroll
            for (int kg2 = 0; kg2 < 4; kg2++) {
                unsigned h0, h1, h2, h3, l0, l1, l2, l3;
                const int off = (kg2 * 16 + lrow) * AS + ks * 16 + lcol;
                ldsm4(h0, h1, h2, h3, sptr(bKh + off));
                ldsm4(l0, l1, l2, l3, sptr(bKl + off));
                mmah(sfr[2 * kg2], qh4, h0, h2);
                mmah(sfr[2 * kg2], qh4, l0, l2);
                mmah(sfr[2 * kg2 + 1], qh4, h1, h3);
                mmah(sfr[2 * kg2 + 1], qh4, l1, l3);
            }
        }

        // ---- mask + zscale + qk write + row max ----
        float rmax[2] = {-INFINITY, -INFINITY};
#pragma unroll
        for (int nt = 0; nt < 8; nt++) {
            const int c0col = nt * 8 + 2 * t;
            const float k0a = __half2float(bKh[c0col * AS]);
            const float k0b = __half2float(bKl[c0col * AS]);
            const float k1a = __half2float(bKh[(c0col + 1) * AS]);
            const float k1b = __half2float(bKl[(c0col + 1) * AS]);
            const float z0 = (k0a == 0.f && k0b == 0.f) ? zfac : 1.f;
            const float z1 = (k1a == 0.f && k1b == 0.f) ? zfac : 1.f;
#pragma unroll
            for (int half = 0; half < 2; half++) {
                const int r = q0 + wr + g + half * 8;
                float2 mk = mask2[(size_t)r * 1024 + kt * 32 + nt * 4 + t];
                float s0 = (sfr[nt][half * 2 + 0] + mk.x * z0) * z0;
                float s1 = (sfr[nt][half * 2 + 1] + mk.y * z1) * z1;
                qk2[((size_t)h * SQ + r) * 1024 + kt * 32 + nt * 4 + t] =
                    make_float2(s0, s1);
                sfr[nt][half * 2 + 0] = s0;
                sfr[nt][half * 2 + 1] = s1;
                rmax[half] = fmaxf(rmax[half], fmaxf(s0, s1));
            }
        }

        // ---- online softmax ----
        float fsc[2];
#pragma unroll
        for (int i = 0; i < 2; i++) {
            float mx = rmax[i];
            mx = fmaxf(mx, __shfl_xor_sync(0xffffffffu, mx, 1));
            mx = fmaxf(mx, __shfl_xor_sync(0xffffffffu, mx, 2));
            const float mn = fmaxf(m_i[i], mx);
            fsc[i] = __expf(m_i[i] - mn);
            m_i[i] = mn;
        }
        float psum[2] = {0.f, 0.f};
#pragma unroll
        for (int nt = 0; nt < 8; nt++)
#pragma unroll
            for (int half = 0; half < 2; half++) {
                float p0 = __expf(sfr[nt][half * 2 + 0] - m_i[half]);
                float p1 = __expf(sfr[nt][half * 2 + 1] - m_i[half]);
                sfr[nt][half * 2 + 0] = p0;
                sfr[nt][half * 2 + 1] = p1;
                psum[half] += p0 + p1;
            }
#pragma unroll
        for (int i = 0; i < 2; i++) {
            float ps = psum[i];
            ps += __shfl_xor_sync(0xffffffffu, ps, 1);
            ps += __shfl_xor_sync(0xffffffffu, ps, 2);
            l_i[i] = l_i[i] * fsc[i] + ps;
        }
#pragma unroll
        for (int nt = 0; nt < 8; nt++) {
            ofr[nt][0] *= fsc[0];
            ofr[nt][1] *= fsc[0];
            ofr[nt][2] *= fsc[1];
            ofr[nt][3] *= fsc[1];
        }

        // ---- O += Ph (Vh + Vl) : P converted hi-only, no split ----
#pragma unroll
        for (int s = 0; s < 4; s++) {
            unsigned pah[4];
            pah[0] = cvt2h(sfr[2 * s][0], sfr[2 * s][1]);
            pah[1] = cvt2h(sfr[2 * s][2], sfr[2 * s][3]);
            pah[2] = cvt2h(sfr[2 * s + 1][0], sfr[2 * s + 1][1]);
            pah[3] = cvt2h(sfr[2 * s + 1][2], sfr[2 * s + 1][3]);
#pragma unroll
            for (int dg = 0; dg < 4; dg++) {
                unsigned h0, h1, h2, h3, l0, l1, l2, l3;
                const int off = (s * 16 + lrow) * AS + dg * 16 + lcol;
                ldsm4t(h0, h1, h2, h3, sptr(bVh + off));
                ldsm4t(l0, l1, l2, l3, sptr(bVl + off));
                mmah(ofr[2 * dg], pah, h0, h1);
                mmah(ofr[2 * dg], pah, l0, l1);
                mmah(ofr[2 * dg + 1], pah, h2, h3);
                mmah(ofr[2 * dg + 1], pah, l2, l3);
            }
        }
        __syncthreads();
        buf ^= 1;
    }

    // ---- write wv (hi only) ----
    const float inv0 = 1.f / l_i[0];
    const float inv1 = 1.f / l_i[1];
#pragma unroll
    for (int nt = 0; nt < 8; nt++) {
        const int d = h * HD + nt * 8 + 2 * t;
#pragma unroll
        for (int half = 0; half < 2; half++) {
            const int r = q0 + wr + g + half * 8;
            const float inv = half ? inv1 : inv0;
            *reinterpret_cast<unsigned*>(g_oh + (size_t)r * DM + d) =
                cvt2h(ofr[nt][half * 2 + 0] * inv, ofr[nt][half * 2 + 1] * inv);
        }
    }
}

// ---------------------------------------------------------------------------
extern "C" void kernel_launch(void* const* d_in, const int* in_sizes, int n_in,
                              void* d_out, int out_size)
{
    const float* x    = (const float*)d_in[0];
    const float* mask = (const float*)d_in[1];
    const float* Wq   = (const float*)d_in[2];
    const float* bq   = (const float*)d_in[3];
    const float* Wk   = (const float*)d_in[4];
    const float* Wv   = (const float*)d_in[5];
    const float* bv   = (const float*)d_in[6];
    const float* Wo   = (const float*)d_in[7];
    const float* bo   = (const float*)d_in[8];
    const float* Zf   = (const float*)d_in[9];
    const float* invf = (const float*)d_in[10];

    float* out = (float*)d_out;                       // [2048, 1024]
    float* qk  = out + (size_t)SQ * DM;               // [16, 2048, 2048]

    const int proj_smem = 2 * 3 * PBUF * 2;           // 61440 B
    const int attn_smem = (9216 + 2 * A_KVB) * 2;     // 92160 B

    static bool attrs_set = false;
    if (!attrs_set) {
        cudaFuncSetAttribute(qkv_gemm, cudaFuncAttributeMaxDynamicSharedMemorySize, proj_smem);
        cudaFuncSetAttribute(out_gemm, cudaFuncAttributeMaxDynamicSharedMemorySize, proj_smem);
        cudaFuncSetAttribute(attn_kernel, cudaFuncAttributeMaxDynamicSharedMemorySize, attn_smem);
        attrs_set = true;
    }

    rope_table<<<256, 256>>>(invf);

    // one fused launch: split x (hi) + all 4 weight matrices (hi+lo)
    split_all<<<dim3((SQ * DM / 4 + 255) / 256, 5), 256>>>(x, Wq, Wk, Wv, Wo);

    qkv_gemm<<<dim3(DM / 128, SQ / 128, 3), 512, proj_smem>>>(bq, bv);

    attn_kernel<<<dim3(SQ / 128, NH), 256, attn_smem>>>(mask, Zf, qk);

    out_gemm<<<dim3(DM / 128, SQ / 128), 512, proj_smem>>>(bo, out);
}

// round 15
// speedup vs baseline: 1.5893x; 1.0682x over previous
#include <cuda_runtime.h>
#include <cuda_fp16.h>
#include <math.h>

#define SQ 2048
#define DM 1024
#define NH 16
#define HD 64

// ---------------- device scratch (no allocs) ----------------
static __device__ float g_cos[SQ * 32];
static __device__ float g_sin[SQ * 32];

static __device__ __half g_xh[SQ * DM];                    // A-side: hi only
static __device__ __half g_Wqh[DM * DM], g_Wql[DM * DM];   // B-side: hi+lo
static __device__ __half g_Wkh[DM * DM], g_Wkl[DM * DM];
static __device__ __half g_Wvh[DM * DM], g_Wvl[DM * DM];
static __device__ __half g_Woh[DM * DM], g_Wol[DM * DM];
static __device__ __half g_qh[NH * SQ * HD];               // Q: hi only
static __device__ __half g_kh[NH * SQ * HD], g_kl[NH * SQ * HD];
static __device__ __half g_vh[NH * SQ * HD];               // V: hi only (consumed fp16)
static __device__ __half g_oh[SQ * DM];                    // wv: hi only

// ---------------- helpers ----------------
__device__ __forceinline__ unsigned sptr(const void* p) {
    return (unsigned)__cvta_generic_to_shared(p);
}
__device__ __forceinline__ void cpa16(void* dst, const void* src) {
    asm volatile("cp.async.cg.shared.global [%0], [%1], 16;"
                 :: "r"(sptr(dst)), "l"(src));
}
__device__ __forceinline__ void cp_commit() {
    asm volatile("cp.async.commit_group;");
}
template <int N>
__device__ __forceinline__ void cp_wait() {
    asm volatile("cp.async.wait_group %0;" :: "n"(N));
}
__device__ __forceinline__ void ldsm4(unsigned& r0, unsigned& r1, unsigned& r2,
                                      unsigned& r3, unsigned a) {
    asm volatile("ldmatrix.sync.aligned.m8n8.x4.shared.b16 {%0,%1,%2,%3},[%4];"
                 : "=r"(r0), "=r"(r1), "=r"(r2), "=r"(r3) : "r"(a));
}
__device__ __forceinline__ void ldsm4t(unsigned& r0, unsigned& r1, unsigned& r2,
                                       unsigned& r3, unsigned a) {
    asm volatile("ldmatrix.sync.aligned.m8n8.x4.trans.shared.b16 {%0,%1,%2,%3},[%4];"
                 : "=r"(r0), "=r"(r1), "=r"(r2), "=r"(r3) : "r"(a));
}
__device__ __forceinline__ void mmah(float* c, const unsigned a[4],
                                     unsigned b0, unsigned b1) {
    asm volatile(
        "mma.sync.aligned.m16n8k16.row.col.f32.f16.f16.f32 "
        "{%0,%1,%2,%3},{%4,%5,%6,%7},{%8,%9},{%0,%1,%2,%3};"
        : "+f"(c[0]), "+f"(c[1]), "+f"(c[2]), "+f"(c[3])
        : "r"(a[0]), "r"(a[1]), "r"(a[2]), "r"(a[3]), "r"(b0), "r"(b1));
}
__device__ __forceinline__ void splith(float x, __half& h, __half& l) {
    h = __float2half_rn(x);
    l = __float2half_rn(x - __half2float(h));
}
__device__ __forceinline__ unsigned pkh(__half a, __half b) {
    __half2 t = __halves2half2(a, b);
    return *reinterpret_cast<unsigned*>(&t);
}
__device__ __forceinline__ unsigned cvt2h(float x, float y) {
    __half2 t = __floats2half2_rn(x, y);
    return *reinterpret_cast<unsigned*>(&t);
}
__device__ __forceinline__ void split2h(float x, float y, unsigned& h, unsigned& l) {
    __half hx, lx, hy, ly;
    splith(x, hx, lx);
    splith(y, hy, ly);
    h = pkh(hx, hy);
    l = pkh(lx, ly);
}

// ---------------------------------------------------------------------------
// RoPE cos/sin table (fp64-accurate)
// ---------------------------------------------------------------------------
__global__ void rope_table(const float* __restrict__ inv_freq)
{
    const int idx = blockIdx.x * 256 + threadIdx.x;
    const int s = idx >> 5;
    const int j = idx & 31;
    const double f = (double)s * (double)inv_freq[j];
    g_cos[idx] = (float)cos(f);
    g_sin[idx] = (float)sin(f);
}

// ---------------------------------------------------------------------------
// Fused split: x -> hi only; weights -> hi+lo. blockIdx.y selects target.
// ---------------------------------------------------------------------------
__global__ void split_all(const float* __restrict__ x,
                          const float* __restrict__ Wq,
                          const float* __restrict__ Wk,
                          const float* __restrict__ Wv,
                          const float* __restrict__ Wo)
{
    const int which = blockIdx.y;
    const float* src;
    __half* h;
    __half* l;
    int n4;
    switch (which) {
        case 0: src = x;  h = g_xh;  l = nullptr; n4 = SQ * DM / 4; break;
        case 1: src = Wq; h = g_Wqh; l = g_Wql;   n4 = DM * DM / 4; break;
        case 2: src = Wk; h = g_Wkh; l = g_Wkl;   n4 = DM * DM / 4; break;
        case 3: src = Wv; h = g_Wvh; l = g_Wvl;   n4 = DM * DM / 4; break;
        default: src = Wo; h = g_Woh; l = g_Wol;  n4 = DM * DM / 4; break;
    }
    const int i = blockIdx.x * 256 + threadIdx.x;
    if (i >= n4) return;
    float4 v = reinterpret_cast<const float4*>(src)[i];
    __half hh[4], ll[4];
    splith(v.x, hh[0], ll[0]);
    splith(v.y, hh[1], ll[1]);
    splith(v.z, hh[2], ll[2]);
    splith(v.w, hh[3], ll[3]);
    reinterpret_cast<uint2*>(h)[i] = make_uint2(pkh(hh[0], hh[1]), pkh(hh[2], hh[3]));
    if (l)
        reinterpret_cast<uint2*>(l)[i] = make_uint2(pkh(ll[0], ll[1]), pkh(ll[2], ll[3]));
}

// ---------------------------------------------------------------------------
// Projection GEMM core (fp16 2-term: C = Ah*Wh^T + Ah*Wl^T), cp.async.
// CTA 128x128, BK=32, 512 threads = 16 warps (4m x 4n), warp tile 32x32.
// ---------------------------------------------------------------------------
#define PK 40
#define PBUF (128 * PK)

#define PJ_ISSUE(kt, b) do {                                                   \
    __half* d0 = smb + (size_t)(b) * 3 * PBUF + cr * PK + cc;                  \
    cpa16(d0,            Ah + (size_t)(m0 + cr) * DM + (kt) * 32 + cc);        \
    cpa16(d0 + PBUF,     Wh + (size_t)(n0 + cr) * DM + (kt) * 32 + cc);        \
    cpa16(d0 + 2 * PBUF, Wl + (size_t)(n0 + cr) * DM + (kt) * 32 + cc);        \
    cp_commit();                                                                \
} while (0)

__device__ __forceinline__ void proj_core(
    const __half* __restrict__ Ah,
    const __half* __restrict__ Wh, const __half* __restrict__ Wl,
    int m0, int n0, __half* smb, float acc[2][4][4], int tid)
{
    const int lane = tid & 31;
    const int wid = tid >> 5;
    const int wm = (wid & 3) * 32;
    const int wn = (wid >> 2) * 32;
    const int lrow = lane & 15;
    const int lcol = (lane >> 4) * 8;
    const int cr = tid >> 2;          // 0..127
    const int cc = (tid & 3) * 8;     // 0,8,16,24

#pragma unroll
    for (int mt = 0; mt < 2; mt++)
#pragma unroll
        for (int nt = 0; nt < 4; nt++)
#pragma unroll
            for (int r = 0; r < 4; r++) acc[mt][nt][r] = 0.f;

    PJ_ISSUE(0, 0);

    int buf = 0;
    for (int kt = 0; kt < DM / 32; kt++) {
        if (kt + 1 < DM / 32) {
            PJ_ISSUE(kt + 1, buf ^ 1);
            cp_wait<1>();
        } else {
            cp_wait<0>();
        }
        __syncthreads();

        __half* sAh = smb + (size_t)buf * 3 * PBUF;
        __half* sWh = sAh + PBUF;
        __half* sWl = sAh + 2 * PBUF;

#pragma unroll
        for (int ks = 0; ks < 2; ks++) {
            unsigned ah[2][4];
#pragma unroll
            for (int mt = 0; mt < 2; mt++) {
                const int off = (wm + mt * 16 + lrow) * PK + ks * 16 + lcol;
                ldsm4(ah[mt][0], ah[mt][1], ah[mt][2], ah[mt][3], sptr(sAh + off));
            }
#pragma unroll
            for (int ng = 0; ng < 2; ng++) {
                unsigned h0, h1, h2, h3, l0, l1, l2, l3;
                const int off = (wn + ng * 16 + lrow) * PK + ks * 16 + lcol;
                ldsm4(h0, h1, h2, h3, sptr(sWh + off));
                ldsm4(l0, l1, l2, l3, sptr(sWl + off));
#pragma unroll
                for (int mt = 0; mt < 2; mt++) {
                    mmah(acc[mt][2 * ng], ah[mt], h0, h2);
                    mmah(acc[mt][2 * ng], ah[mt], l0, l2);
                    mmah(acc[mt][2 * ng + 1], ah[mt], h1, h3);
                    mmah(acc[mt][2 * ng + 1], ah[mt], l1, l3);
                }
            }
        }
        __syncthreads();
        buf ^= 1;
    }
}

// ---------------------------------------------------------------------------
// Fused QKV GEMM + bias + RoPE + scale; q/v -> hi only, k -> hi+lo.
// ---------------------------------------------------------------------------
__global__ void __launch_bounds__(512) qkv_gemm(
    const float* __restrict__ bq, const float* __restrict__ bv)
{
    extern __shared__ __align__(16) __half smb[];
    const int tid = threadIdx.x;
    const int z = blockIdx.z;
    const int m0 = blockIdx.y * 128;
    const int n0 = blockIdx.x * 128;

    const __half* Wh = (z == 0) ? g_Wqh : (z == 1) ? g_Wkh : g_Wvh;
    const __half* Wl = (z == 0) ? g_Wql : (z == 1) ? g_Wkl : g_Wvl;
    const float* bias = (z == 0) ? bq : (z == 2) ? bv : nullptr;
    __half* outh = (z == 0) ? g_qh : (z == 1) ? g_kh : g_vh;

    float acc[2][4][4];
    proj_core(g_xh, Wh, Wl, m0, n0, smb, acc, tid);

    const int lane = tid & 31;
    const int wid = tid >> 5;
    const int g = lane >> 2;
    const int t = lane & 3;
    const int wm = (wid & 3) * 32;
    const int wn = (wid >> 2) * 32;
    const float rsc = 0.35355339059327373f;   // 64^(-1/4)

#pragma unroll
    for (int mt = 0; mt < 2; mt++) {
#pragma unroll
        for (int nt = 0; nt < 4; nt++) {
            const int n = n0 + wn + nt * 8 + 2 * t;
            const int hh = n >> 6;
            const int d = n & 63;
            const float b0v = bias ? bias[n] : 0.f;
            const float b1v = bias ? bias[n + 1] : 0.f;
#pragma unroll
            for (int half = 0; half < 2; half++) {
                const int m = m0 + wm + mt * 16 + g + half * 8;
                float a = acc[mt][nt][half * 2 + 0] + b0v;
                float b = acc[mt][nt][half * 2 + 1] + b1v;
                const size_t off = ((size_t)hh * SQ + m) * HD + d;
                if (z < 2) {
                    const int pi = d >> 1;
                    const float c = g_cos[m * 32 + pi];
                    const float s = g_sin[m * 32 + pi];
                    const float ra = rsc * (a * c - b * s);
                    const float rb = rsc * (a * s + b * c);
                    if (z == 0) {
                        *reinterpret_cast<unsigned*>(outh + off) = cvt2h(ra, rb);
                    } else {
                        unsigned hp, lp;
                        split2h(ra, rb, hp, lp);
                        *reinterpret_cast<unsigned*>(outh + off) = hp;
                        *reinterpret_cast<unsigned*>(g_kl + off) = lp;
                    }
                } else {
                    *reinterpret_cast<unsigned*>(outh + off) = cvt2h(a, b);
                }
            }
        }
    }
}

// ---------------------------------------------------------------------------
// Output projection: out = wv(hi) @ Wo(hi+lo)^T + bo, fp32 row-major
// ---------------------------------------------------------------------------
__global__ void __launch_bounds__(512) out_gemm(
    const float* __restrict__ bo, float* __restrict__ C)
{
    extern __shared__ __align__(16) __half smb[];
    const int tid = threadIdx.x;
    const int m0 = blockIdx.y * 128;
    const int n0 = blockIdx.x * 128;

    float acc[2][4][4];
    proj_core(g_oh, g_Woh, g_Wol, m0, n0, smb, acc, tid);

    const int lane = tid & 31;
    const int wid = tid >> 5;
    const int g = lane >> 2;
    const int t = lane & 3;
    const int wm = (wid & 3) * 32;
    const int wn = (wid >> 2) * 32;

#pragma unroll
    for (int mt = 0; mt < 2; mt++) {
#pragma unroll
        for (int nt = 0; nt < 4; nt++) {
            const int n = n0 + wn + nt * 8 + 2 * t;
            const float b0v = bo[n], b1v = bo[n + 1];
#pragma unroll
            for (int half = 0; half < 2; half++) {
                const int m = m0 + wm + mt * 16 + g + half * 8;
                *reinterpret_cast<float2*>(C + (size_t)m * DM + n) =
                    make_float2(acc[mt][nt][half * 2 + 0] + b0v,
                                acc[mt][nt][half * 2 + 1] + b1v);
            }
        }
    }
}

// ---------------------------------------------------------------------------
// Attention. CTA: 1 head x 128 q rows, 256 threads = 8 warps x 16 rows.
// S = Qh*(Kh+Kl)^T (2-term); O += Ph*Vh (1-term; V precision paid at store).
// grid = (NH, SQ/128): heads contiguous -> mask slice L2 reuse.
// smem halfs: sQh[128*72] + 2 x {Kh,Kl,Vh}[64*72] = 36864 (73.7 KB).
// __maxnreg__(128) -> 2 CTAs/SM.
// ---------------------------------------------------------------------------
#define AS 72
#define A_QH 0
#define A_KV 9216
#define A_KVB 13824

__global__ void __maxnreg__(128) attn_kernel(
    const float* __restrict__ mask, const float* __restrict__ Zf,
    float* __restrict__ qk_out)
{
    extern __shared__ __align__(16) __half smb[];
    __half* sQh = smb + A_QH;

    const int tid = threadIdx.x;
    const int lane = tid & 31;
    const int wid = tid >> 5;
    const int g = lane >> 2;
    const int t = lane & 3;
    const int lrow = lane & 15;
    const int lcol = (lane >> 4) * 8;
    const int wr = wid * 16;
    const int h = blockIdx.x;                 // head is FAST dim (mask L2 reuse)
    const int q0 = blockIdx.y * 128;

    const float zfac = fminf(fmaxf(log1pf(expf(Zf[0])), 1e-5f), 1e-4f);

    // ---- prologue: Q copy (hi only) + KV tile 0 ----
#pragma unroll
    for (int i = 0; i < 4; i++) {
        const int idx = tid + i * 256;           // 0..1023
        const int r = idx >> 3;
        const int c = (idx & 7) * 8;
        cpa16(sQh + r * AS + c, g_qh + ((size_t)h * SQ + q0 + r) * HD + c);
    }
    {
        __half* kb = smb + A_KV;
#pragma unroll
        for (int i = 0; i < 2; i++) {
            const int idx = tid + i * 256;        // 0..511
            const int r = idx >> 3;
            const int c = (idx & 7) * 8;
            const size_t so = ((size_t)h * SQ + r) * HD + c;
            cpa16(kb +        r * AS + c, g_kh + so);
            cpa16(kb + 4608 + r * AS + c, g_kl + so);
            cpa16(kb + 9216 + r * AS + c, g_vh + so);
        }
        cp_commit();
    }

    float ofr[8][4];
    float m_i[2], l_i[2];
#pragma unroll
    for (int nt = 0; nt < 8; nt++)
#pragma unroll
        for (int r = 0; r < 4; r++) ofr[nt][r] = 0.f;
    m_i[0] = m_i[1] = -INFINITY;
    l_i[0] = l_i[1] = 0.f;

    const float2* mask2 = reinterpret_cast<const float2*>(mask);
    float2* qk2 = reinterpret_cast<float2*>(qk_out);

    int buf = 0;
    for (int kt = 0; kt < SQ / 64; kt++) {
        if (kt + 1 < SQ / 64) {
            __half* kb = smb + A_KV + (size_t)(buf ^ 1) * A_KVB;
#pragma unroll
            for (int i = 0; i < 2; i++) {
                const int idx = tid + i * 256;
                const int r = idx >> 3;
                const int c = (idx & 7) * 8;
                const size_t so = ((size_t)h * SQ + (kt + 1) * 64 + r) * HD + c;
                cpa16(kb +        r * AS + c, g_kh + so);
                cpa16(kb + 4608 + r * AS + c, g_kl + so);
                cpa16(kb + 9216 + r * AS + c, g_vh + so);
            }
            cp_commit();
            cp_wait<1>();
        } else {
            cp_wait<0>();
        }
        __syncthreads();

        __half* bKh = smb + A_KV + (size_t)buf * A_KVB;
        __half* bKl = bKh + 4608;
        __half* bVh = bKh + 9216;

        // ---- S = Qh (Kh + Kl)^T ----
        float sfr[8][4];
#pragma unroll
        for (int nt = 0; nt < 8; nt++)
#pragma unroll
            for (int r = 0; r < 4; r++) sfr[nt][r] = 0.f;

#pragma unroll
        for (int ks = 0; ks < 4; ks++) {
            unsigned qh4[4];
            ldsm4(qh4[0], qh4[1], qh4[2], qh4[3],
                  sptr(sQh + (wr + lrow) * AS + ks * 16 + lcol));
#pragma unroll
            for (int kg2 = 0; kg2 < 4; kg2++) {
                unsigned h0, h1, h2, h3, l0, l1, l2, l3;
                const int off = (kg2 * 16 + lrow) * AS + ks * 16 + lcol;
                ldsm4(h0, h1, h2, h3, sptr(bKh + off));
                ldsm4(l0, l1, l2, l3, sptr(bKl + off));
                mmah(sfr[2 * kg2], qh4, h0, h2);
                mmah(sfr[2 * kg2], qh4, l0, l2);
                mmah(sfr[2 * kg2 + 1], qh4, h1, h3);
                mmah(sfr[2 * kg2 + 1], qh4, l1, l3);
            }
        }

        // ---- mask + zscale + qk write + row max ----
        float rmax[2] = {-INFINITY, -INFINITY};
#pragma unroll
        for (int nt = 0; nt < 8; nt++) {
            const int c0col = nt * 8 + 2 * t;
            const float k0a = __half2float(bKh[c0col * AS]);
            const float k0b = __half2float(bKl[c0col * AS]);
            const float k1a = __half2float(bKh[(c0col + 1) * AS]);
            const float k1b = __half2float(bKl[(c0col + 1) * AS]);
            const float z0 = (k0a == 0.f && k0b == 0.f) ? zfac : 1.f;
            const float z1 = (k1a == 0.f && k1b == 0.f) ? zfac : 1.f;
#pragma unroll
            for (int half = 0; half < 2; half++) {
                const int r = q0 + wr + g + half * 8;
                float2 mk = mask2[(size_t)r * 1024 + kt * 32 + nt * 4 + t];
                float s0 = (sfr[nt][half * 2 + 0] + mk.x * z0) * z0;
                float s1 = (sfr[nt][half * 2 + 1] + mk.y * z1) * z1;
                qk2[((size_t)h * SQ + r) * 1024 + kt * 32 + nt * 4 + t] =
                    make_float2(s0, s1);
                sfr[nt][half * 2 + 0] = s0;
                sfr[nt][half * 2 + 1] = s1;
                rmax[half] = fmaxf(rmax[half], fmaxf(s0, s1));
            }
        }

        // ---- online softmax ----
        float fsc[2];
#pragma unroll
        for (int i = 0; i < 2; i++) {
            float mx = rmax[i];
            mx = fmaxf(mx, __shfl_xor_sync(0xffffffffu, mx, 1));
            mx = fmaxf(mx, __shfl_xor_sync(0xffffffffu, mx, 2));
            const float mn = fmaxf(m_i[i], mx);
            fsc[i] = __expf(m_i[i] - mn);
            m_i[i] = mn;
        }
        float psum[2] = {0.f, 0.f};
#pragma unroll
        for (int nt = 0; nt < 8; nt++)
#pragma unroll
            for (int half = 0; half < 2; half++) {
                float p0 = __expf(sfr[nt][half * 2 + 0] - m_i[half]);
                float p1 = __expf(sfr[nt][half * 2 + 1] - m_i[half]);
                sfr[nt][half * 2 + 0] = p0;
                sfr[nt][half * 2 + 1] = p1;
                psum[half] += p0 + p1;
            }
#pragma unroll
        for (int i = 0; i < 2; i++) {
            float ps = psum[i];
            ps += __shfl_xor_sync(0xffffffffu, ps, 1);
            ps += __shfl_xor_sync(0xffffffffu, ps, 2);
            l_i[i] = l_i[i] * fsc[i] + ps;
        }
#pragma unroll
        for (int nt = 0; nt < 8; nt++) {
            ofr[nt][0] *= fsc[0];
            ofr[nt][1] *= fsc[0];
            ofr[nt][2] *= fsc[1];
            ofr[nt][3] *= fsc[1];
        }

        // ---- O += Ph * Vh (single term) ----
#pragma unroll
        for (int s = 0; s < 4; s++) {
            unsigned pah[4];
            pah[0] = cvt2h(sfr[2 * s][0], sfr[2 * s][1]);
            pah[1] = cvt2h(sfr[2 * s][2], sfr[2 * s][3]);
            pah[2] = cvt2h(sfr[2 * s + 1][0], sfr[2 * s + 1][1]);
            pah[3] = cvt2h(sfr[2 * s + 1][2], sfr[2 * s + 1][3]);
#pragma unroll
            for (int dg = 0; dg < 4; dg++) {
                unsigned h0, h1, h2, h3;
                const int off = (s * 16 + lrow) * AS + dg * 16 + lcol;
                ldsm4t(h0, h1, h2, h3, sptr(bVh + off));
                mmah(ofr[2 * dg], pah, h0, h1);
                mmah(ofr[2 * dg + 1], pah, h2, h3);
            }
        }
        __syncthreads();
        buf ^= 1;
    }

    // ---- write wv (hi only) ----
    const float inv0 = 1.f / l_i[0];
    const float inv1 = 1.f / l_i[1];
#pragma unroll
    for (int nt = 0; nt < 8; nt++) {
        const int d = h * HD + nt * 8 + 2 * t;
#pragma unroll
        for (int half = 0; half < 2; half++) {
            const int r = q0 + wr + g + half * 8;
            const float inv = half ? inv1 : inv0;
            *reinterpret_cast<unsigned*>(g_oh + (size_t)r * DM + d) =
                cvt2h(ofr[nt][half * 2 + 0] * inv, ofr[nt][half * 2 + 1] * inv);
        }
    }
}

// ---------------------------------------------------------------------------
extern "C" void kernel_launch(void* const* d_in, const int* in_sizes, int n_in,
                              void* d_out, int out_size)
{
    const float* x    = (const float*)d_in[0];
    const float* mask = (const float*)d_in[1];
    const float* Wq   = (const float*)d_in[2];
    const float* bq   = (const float*)d_in[3];
    const float* Wk   = (const float*)d_in[4];
    const float* Wv   = (const float*)d_in[5];
    const float* bv   = (const float*)d_in[6];
    const float* Wo   = (const float*)d_in[7];
    const float* bo   = (const float*)d_in[8];
    const float* Zf   = (const float*)d_in[9];
    const float* invf = (const float*)d_in[10];

    float* out = (float*)d_out;                       // [2048, 1024]
    float* qk  = out + (size_t)SQ * DM;               // [16, 2048, 2048]

    const int proj_smem = 2 * 3 * PBUF * 2;           // 61440 B
    const int attn_smem = (9216 + 2 * A_KVB) * 2;     // 73728 B

    static bool attrs_set = false;
    if (!attrs_set) {
        cudaFuncSetAttribute(qkv_gemm, cudaFuncAttributeMaxDynamicSharedMemorySize, proj_smem);
        cudaFuncSetAttribute(out_gemm, cudaFuncAttributeMaxDynamicSharedMemorySize, proj_smem);
        cudaFuncSetAttribute(attn_kernel, cudaFuncAttributeMaxDynamicSharedMemorySize, attn_smem);
        attrs_set = true;
    }

    rope_table<<<256, 256>>>(invf);

    split_all<<<dim3((SQ * DM / 4 + 255) / 256, 5), 256>>>(x, Wq, Wk, Wv, Wo);

    qkv_gemm<<<dim3(DM / 128, SQ / 128, 3), 512, proj_smem>>>(bq, bv);

    attn_kernel<<<dim3(NH, SQ / 128), 256, attn_smem>>>(mask, Zf, qk);

    out_gemm<<<dim3(DM / 128, SQ / 128), 512, proj_smem>>>(bo, out);
}

// round 17
// speedup vs baseline: 1.6471x; 1.0364x over previous
#include <cuda_runtime.h>
#include <cuda_fp16.h>
#include <math.h>

#define SQ 2048
#define DM 1024
#define NH 16
#define HD 64

// ---------------- device scratch (no allocs) ----------------
static __device__ float g_cos[SQ * 32];
static __device__ float g_sin[SQ * 32];

static __device__ __half g_xh[SQ * DM];                    // A-side: hi only
static __device__ __half g_Wqh[DM * DM], g_Wql[DM * DM];   // B-side: hi+lo
static __device__ __half g_Wkh[DM * DM], g_Wkl[DM * DM];
static __device__ __half g_Wvh[DM * DM], g_Wvl[DM * DM];
static __device__ __half g_Woh[DM * DM], g_Wol[DM * DM];
static __device__ __half g_qh[NH * SQ * HD], g_ql[NH * SQ * HD];  // Q: hi+lo
static __device__ __half g_kh[NH * SQ * HD];               // K: hi only
static __device__ __half g_vh[NH * SQ * HD];               // V: hi only
static __device__ __half g_oh[SQ * DM];                    // wv: hi only

// ---------------- helpers ----------------
__device__ __forceinline__ unsigned sptr(const void* p) {
    return (unsigned)__cvta_generic_to_shared(p);
}
__device__ __forceinline__ void cpa16(void* dst, const void* src) {
    asm volatile("cp.async.cg.shared.global [%0], [%1], 16;"
                 :: "r"(sptr(dst)), "l"(src));
}
__device__ __forceinline__ void cp_commit() {
    asm volatile("cp.async.commit_group;");
}
template <int N>
__device__ __forceinline__ void cp_wait() {
    asm volatile("cp.async.wait_group %0;" :: "n"(N));
}
__device__ __forceinline__ void ldsm4(unsigned& r0, unsigned& r1, unsigned& r2,
                                      unsigned& r3, unsigned a) {
    asm volatile("ldmatrix.sync.aligned.m8n8.x4.shared.b16 {%0,%1,%2,%3},[%4];"
                 : "=r"(r0), "=r"(r1), "=r"(r2), "=r"(r3) : "r"(a));
}
__device__ __forceinline__ void ldsm4t(unsigned& r0, unsigned& r1, unsigned& r2,
                                       unsigned& r3, unsigned a) {
    asm volatile("ldmatrix.sync.aligned.m8n8.x4.trans.shared.b16 {%0,%1,%2,%3},[%4];"
                 : "=r"(r0), "=r"(r1), "=r"(r2), "=r"(r3) : "r"(a));
}
__device__ __forceinline__ void mmah(float* c, const unsigned a[4],
                                     unsigned b0, unsigned b1) {
    asm volatile(
        "mma.sync.aligned.m16n8k16.row.col.f32.f16.f16.f32 "
        "{%0,%1,%2,%3},{%4,%5,%6,%7},{%8,%9},{%0,%1,%2,%3};"
        : "+f"(c[0]), "+f"(c[1]), "+f"(c[2]), "+f"(c[3])
        : "r"(a[0]), "r"(a[1]), "r"(a[2]), "r"(a[3]), "r"(b0), "r"(b1));
}
__device__ __forceinline__ void splith(float x, __half& h, __half& l) {
    h = __float2half_rn(x);
    l = __float2half_rn(x - __half2float(h));
}
__device__ __forceinline__ unsigned pkh(__half a, __half b) {
    __half2 t = __halves2half2(a, b);
    return *reinterpret_cast<unsigned*>(&t);
}
__device__ __forceinline__ unsigned cvt2h(float x, float y) {
    __half2 t = __floats2half2_rn(x, y);
    return *reinterpret_cast<unsigned*>(&t);
}
__device__ __forceinline__ void split2h(float x, float y, unsigned& h, unsigned& l) {
    __half hx, lx, hy, ly;
    splith(x, hx, lx);
    splith(y, hy, ly);
    h = pkh(hx, hy);
    l = pkh(lx, ly);
}

// ---------------------------------------------------------------------------
// RoPE cos/sin table (fp64-accurate)
// ---------------------------------------------------------------------------
__global__ void rope_table(const float* __restrict__ inv_freq)
{
    const int idx = blockIdx.x * 256 + threadIdx.x;
    const int s = idx >> 5;
    const int j = idx & 31;
    const double f = (double)s * (double)inv_freq[j];
    g_cos[idx] = (float)cos(f);
    g_sin[idx] = (float)sin(f);
}

// ---------------------------------------------------------------------------
// Fused split: x -> hi only; weights -> hi+lo.
// ---------------------------------------------------------------------------
__global__ void split_all(const float* __restrict__ x,
                          const float* __restrict__ Wq,
                          const float* __restrict__ Wk,
                          const float* __restrict__ Wv,
                          const float* __restrict__ Wo)
{
    const int which = blockIdx.y;
    const float* src;
    __half* h;
    __half* l;
    int n4;
    switch (which) {
        case 0: src = x;  h = g_xh;  l = nullptr; n4 = SQ * DM / 4; break;
        case 1: src = Wq; h = g_Wqh; l = g_Wql;   n4 = DM * DM / 4; break;
        case 2: src = Wk; h = g_Wkh; l = g_Wkl;   n4 = DM * DM / 4; break;
        case 3: src = Wv; h = g_Wvh; l = g_Wvl;   n4 = DM * DM / 4; break;
        default: src = Wo; h = g_Woh; l = g_Wol;  n4 = DM * DM / 4; break;
    }
    const int i = blockIdx.x * 256 + threadIdx.x;
    if (i >= n4) return;
    float4 v = reinterpret_cast<const float4*>(src)[i];
    __half hh[4], ll[4];
    splith(v.x, hh[0], ll[0]);
    splith(v.y, hh[1], ll[1]);
    splith(v.z, hh[2], ll[2]);
    splith(v.w, hh[3], ll[3]);
    reinterpret_cast<uint2*>(h)[i] = make_uint2(pkh(hh[0], hh[1]), pkh(hh[2], hh[3]));
    if (l)
        reinterpret_cast<uint2*>(l)[i] = make_uint2(pkh(ll[0], ll[1]), pkh(ll[2], ll[3]));
}

// ---------------------------------------------------------------------------
// Projection GEMM core (fp16 2-term: C = Ah*Wh^T + Ah*Wl^T), cp.async.
// CTA 128x128, BK=32, 512 threads = 16 warps (4m x 4n), warp tile 32x32.
// ---------------------------------------------------------------------------
#define PK 40
#define PBUF (128 * PK)

#define PJ_ISSUE(kt, b) do {                                                   \
    __half* d0 = smb + (size_t)(b) * 3 * PBUF + cr * PK + cc;                  \
    cpa16(d0,            Ah + (size_t)(m0 + cr) * DM + (kt) * 32 + cc);        \
    cpa16(d0 + PBUF,     Wh + (size_t)(n0 + cr) * DM + (kt) * 32 + cc);        \
    cpa16(d0 + 2 * PBUF, Wl + (size_t)(n0 + cr) * DM + (kt) * 32 + cc);        \
    cp_commit();                                                                \
} while (0)

__device__ __forceinline__ void proj_core(
    const __half* __restrict__ Ah,
    const __half* __restrict__ Wh, const __half* __restrict__ Wl,
    int m0, int n0, __half* smb, float acc[2][4][4], int tid)
{
    const int lane = tid & 31;
    const int wid = tid >> 5;
    const int wm = (wid & 3) * 32;
    const int wn = (wid >> 2) * 32;
    const int lrow = lane & 15;
    const int lcol = (lane >> 4) * 8;
    const int cr = tid >> 2;          // 0..127
    const int cc = (tid & 3) * 8;     // 0,8,16,24

#pragma unroll
    for (int mt = 0; mt < 2; mt++)
#pragma unroll
        for (int nt = 0; nt < 4; nt++)
#pragma unroll
            for (int r = 0; r < 4; r++) acc[mt][nt][r] = 0.f;

    PJ_ISSUE(0, 0);

    int buf = 0;
    for (int kt = 0; kt < DM / 32; kt++) {
        if (kt + 1 < DM / 32) {
            PJ_ISSUE(kt + 1, buf ^ 1);
            cp_wait<1>();
        } else {
            cp_wait<0>();
        }
        __syncthreads();

        __half* sAh = smb + (size_t)buf * 3 * PBUF;
        __half* sWh = sAh + PBUF;
        __half* sWl = sAh + 2 * PBUF;

#pragma unroll
        for (int ks = 0; ks < 2; ks++) {
            unsigned ah[2][4];
#pragma unroll
            for (int mt = 0; mt < 2; mt++) {
                const int off = (wm + mt * 16 + lrow) * PK + ks * 16 + lcol;
                ldsm4(ah[mt][0], ah[mt][1], ah[mt][2], ah[mt][3], sptr(sAh + off));
            }
#pragma unroll
            for (int ng = 0; ng < 2; ng++) {
                unsigned h0, h1, h2, h3, l0, l1, l2, l3;
                const int off = (wn + ng * 16 + lrow) * PK + ks * 16 + lcol;
                ldsm4(h0, h1, h2, h3, sptr(sWh + off));
                ldsm4(l0, l1, l2, l3, sptr(sWl + off));
#pragma unroll
                for (int mt = 0; mt < 2; mt++) {
                    mmah(acc[mt][2 * ng], ah[mt], h0, h2);
                    mmah(acc[mt][2 * ng], ah[mt], l0, l2);
                    mmah(acc[mt][2 * ng + 1], ah[mt], h1, h3);
                    mmah(acc[mt][2 * ng + 1], ah[mt], l1, l3);
                }
            }
        }
        __syncthreads();
        buf ^= 1;
    }
}

// ---------------------------------------------------------------------------
// Fused QKV GEMM + bias + RoPE + scale.
// q -> hi+lo (2-term consumer in attention), k/v -> hi only.
// ---------------------------------------------------------------------------
__global__ void __launch_bounds__(512) qkv_gemm(
    const float* __restrict__ bq, const float* __restrict__ bv)
{
    extern __shared__ __align__(16) __half smb[];
    const int tid = threadIdx.x;
    const int z = blockIdx.z;
    const int m0 = blockIdx.y * 128;
    const int n0 = blockIdx.x * 128;

    const __half* Wh = (z == 0) ? g_Wqh : (z == 1) ? g_Wkh : g_Wvh;
    const __half* Wl = (z == 0) ? g_Wql : (z == 1) ? g_Wkl : g_Wvl;
    const float* bias = (z == 0) ? bq : (z == 2) ? bv : nullptr;
    __half* outh = (z == 0) ? g_qh : (z == 1) ? g_kh : g_vh;

    float acc[2][4][4];
    proj_core(g_xh, Wh, Wl, m0, n0, smb, acc, tid);

    const int lane = tid & 31;
    const int wid = tid >> 5;
    const int g = lane >> 2;
    const int t = lane & 3;
    const int wm = (wid & 3) * 32;
    const int wn = (wid >> 2) * 32;
    const float rsc = 0.35355339059327373f;   // 64^(-1/4)

#pragma unroll
    for (int mt = 0; mt < 2; mt++) {
#pragma unroll
        for (int nt = 0; nt < 4; nt++) {
            const int n = n0 + wn + nt * 8 + 2 * t;
            const int hh = n >> 6;
            const int d = n & 63;
            const float b0v = bias ? bias[n] : 0.f;
            const float b1v = bias ? bias[n + 1] : 0.f;
#pragma unroll
            for (int half = 0; half < 2; half++) {
                const int m = m0 + wm + mt * 16 + g + half * 8;
                float a = acc[mt][nt][half * 2 + 0] + b0v;
                float b = acc[mt][nt][half * 2 + 1] + b1v;
                const size_t off = ((size_t)hh * SQ + m) * HD + d;
                if (z < 2) {
                    const int pi = d >> 1;
                    const float c = g_cos[m * 32 + pi];
                    const float s = g_sin[m * 32 + pi];
                    const float ra = rsc * (a * c - b * s);
                    const float rb = rsc * (a * s + b * c);
                    if (z == 0) {
                        unsigned hp, lp;
                        split2h(ra, rb, hp, lp);
                        *reinterpret_cast<unsigned*>(outh + off) = hp;
                        *reinterpret_cast<unsigned*>(g_ql + off) = lp;
                    } else {
                        *reinterpret_cast<unsigned*>(outh + off) = cvt2h(ra, rb);
                    }
                } else {
                    *reinterpret_cast<unsigned*>(outh + off) = cvt2h(a, b);
                }
            }
        }
    }
}

// ---------------------------------------------------------------------------
// Output projection: out = wv(hi) @ Wo(hi+lo)^T + bo, fp32 row-major
// ---------------------------------------------------------------------------
__global__ void __launch_bounds__(512) out_gemm(
    const float* __restrict__ bo, float* __restrict__ C)
{
    extern __shared__ __align__(16) __half smb[];
    const int tid = threadIdx.x;
    const int m0 = blockIdx.y * 128;
    const int n0 = blockIdx.x * 128;

    float acc[2][4][4];
    proj_core(g_oh, g_Woh, g_Wol, m0, n0, smb, acc, tid);

    const int lane = tid & 31;
    const int wid = tid >> 5;
    const int g = lane >> 2;
    const int t = lane & 3;
    const int wm = (wid & 3) * 32;
    const int wn = (wid >> 2) * 32;

#pragma unroll
    for (int mt = 0; mt < 2; mt++) {
#pragma unroll
        for (int nt = 0; nt < 4; nt++) {
            const int n = n0 + wn + nt * 8 + 2 * t;
            const float b0v = bo[n], b1v = bo[n + 1];
#pragma unroll
            for (int half = 0; half < 2; half++) {
                const int m = m0 + wm + mt * 16 + g + half * 8;
                *reinterpret_cast<float2*>(C + (size_t)m * DM + n) =
                    make_float2(acc[mt][nt][half * 2 + 0] + b0v,
                                acc[mt][nt][half * 2 + 1] + b1v);
            }
        }
    }
}

// ---------------------------------------------------------------------------
// Attention. CTA: 1 head x 128 q rows, 256 threads = 8 warps x 16 rows.
// S = (Qh+Ql)*Kh^T: Q carries the split (Q fragments are reused across all
// key n-tiles -> 24 S-phase ldsm/warp-tile vs 36 for K-side split).
// O += Ph*Vh. grid = (NH, SQ/128) for mask L2 reuse.
// smem halfs: sQh/sQl[128*72] + 2 x {Kh,Vh}[64*72] = 36864 (73.7 KB).
// __maxnreg__(128) -> 2 CTAs/SM. (Resubmission of R16: infra flake, not code.)
// ---------------------------------------------------------------------------
#define AS 72
#define A_QH 0
#define A_QL 9216
#define A_KV 18432
#define A_KVB 9216

__global__ void __maxnreg__(128) attn_kernel(
    const float* __restrict__ mask, const float* __restrict__ Zf,
    float* __restrict__ qk_out)
{
    extern __shared__ __align__(16) __half smb[];
    __half* sQh = smb + A_QH;
    __half* sQl = smb + A_QL;

    const int tid = threadIdx.x;
    const int lane = tid & 31;
    const int wid = tid >> 5;
    const int g = lane >> 2;
    const int t = lane & 3;
    const int lrow = lane & 15;
    const int lcol = (lane >> 4) * 8;
    const int wr = wid * 16;
    const int h = blockIdx.x;                 // head is FAST dim (mask L2 reuse)
    const int q0 = blockIdx.y * 128;

    const float zfac = fminf(fmaxf(log1pf(expf(Zf[0])), 1e-5f), 1e-4f);

    // ---- prologue: Q copy (hi+lo) + KV tile 0 ----
#pragma unroll
    for (int i = 0; i < 4; i++) {
        const int idx = tid + i * 256;           // 0..1023
        const int r = idx >> 3;
        const int c = (idx & 7) * 8;
        const size_t so = ((size_t)h * SQ + q0 + r) * HD + c;
        cpa16(sQh + r * AS + c, g_qh + so);
        cpa16(sQl + r * AS + c, g_ql + so);
    }
    {
        __half* kb = smb + A_KV;
#pragma unroll
        for (int i = 0; i < 2; i++) {
            const int idx = tid + i * 256;        // 0..511
            const int r = idx >> 3;
            const int c = (idx & 7) * 8;
            const size_t so = ((size_t)h * SQ + r) * HD + c;
            cpa16(kb +        r * AS + c, g_kh + so);
            cpa16(kb + 4608 + r * AS + c, g_vh + so);
        }
        cp_commit();
    }

    float ofr[8][4];
    float m_i[2], l_i[2];
#pragma unroll
    for (int nt = 0; nt < 8; nt++)
#pragma unroll
        for (int r = 0; r < 4; r++) ofr[nt][r] = 0.f;
    m_i[0] = m_i[1] = -INFINITY;
    l_i[0] = l_i[1] = 0.f;

    const float2* mask2 = reinterpret_cast<const float2*>(mask);
    float2* qk2 = reinterpret_cast<float2*>(qk_out);

    int buf = 0;
    for (int kt = 0; kt < SQ / 64; kt++) {
        if (kt + 1 < SQ / 64) {
            __half* kb = smb + A_KV + (size_t)(buf ^ 1) * A_KVB;
#pragma unroll
            for (int i = 0; i < 2; i++) {
                const int idx = tid + i * 256;
                const int r = idx >> 3;
                const int c = (idx & 7) * 8;
                const size_t so = ((size_t)h * SQ + (kt + 1) * 64 + r) * HD + c;
                cpa16(kb +        r * AS + c, g_kh + so);
                cpa16(kb + 4608 + r * AS + c, g_vh + so);
            }
            cp_commit();
            cp_wait<1>();
        } else {
            cp_wait<0>();
        }
        __syncthreads();

        __half* bKh = smb + A_KV + (size_t)buf * A_KVB;
        __half* bVh = bKh + 4608;

        // ---- S = (Qh + Ql) Kh^T ----
        float sfr[8][4];
#pragma unroll
        for (int nt = 0; nt < 8; nt++)
#pragma unroll
            for (int r = 0; r < 4; r++) sfr[nt][r] = 0.f;

#pragma unroll
        for (int ks = 0; ks < 4; ks++) {
            unsigned qh4[4], ql4[4];
            const int qoff = (wr + lrow) * AS + ks * 16 + lcol;
            ldsm4(qh4[0], qh4[1], qh4[2], qh4[3], sptr(sQh + qoff));
            ldsm4(ql4[0], ql4[1], ql4[2], ql4[3], sptr(sQl + qoff));
#pragma unroll
            for (int kg2 = 0; kg2 < 4; kg2++) {
                unsigned h0, h1, h2, h3;
                const int off = (kg2 * 16 + lrow) * AS + ks * 16 + lcol;
                ldsm4(h0, h1, h2, h3, sptr(bKh + off));
                mmah(sfr[2 * kg2], qh4, h0, h2);
                mmah(sfr[2 * kg2], ql4, h0, h2);
                mmah(sfr[2 * kg2 + 1], qh4, h1, h3);
                mmah(sfr[2 * kg2 + 1], ql4, h1, h3);
            }
        }

        // ---- mask + zscale + qk write + row max ----
        float rmax[2] = {-INFINITY, -INFINITY};
#pragma unroll
        for (int nt = 0; nt < 8; nt++) {
            const int c0col = nt * 8 + 2 * t;
            const float k0a = __half2float(bKh[c0col * AS]);
            const float k1a = __half2float(bKh[(c0col + 1) * AS]);
            const float z0 = (k0a == 0.f) ? zfac : 1.f;
            const float z1 = (k1a == 0.f) ? zfac : 1.f;
#pragma unroll
            for (int half = 0; half < 2; half++) {
                const int r = q0 + wr + g + half * 8;
                float2 mk = mask2[(size_t)r * 1024 + kt * 32 + nt * 4 + t];
                float s0 = (sfr[nt][half * 2 + 0] + mk.x * z0) * z0;
                float s1 = (sfr[nt][half * 2 + 1] + mk.y * z1) * z1;
                qk2[((size_t)h * SQ + r) * 1024 + kt * 32 + nt * 4 + t] =
                    make_float2(s0, s1);
                sfr[nt][half * 2 + 0] = s0;
                sfr[nt][half * 2 + 1] = s1;
                rmax[half] = fmaxf(rmax[half], fmaxf(s0, s1));
            }
        }

        // ---- online softmax ----
        float fsc[2];
#pragma unroll
        for (int i = 0; i < 2; i++) {
            float mx = rmax[i];
            mx = fmaxf(mx, __shfl_xor_sync(0xffffffffu, mx, 1));
            mx = fmaxf(mx, __shfl_xor_sync(0xffffffffu, mx, 2));
            const float mn = fmaxf(m_i[i], mx);
            fsc[i] = __expf(m_i[i] - mn);
            m_i[i] = mn;
        }
        float psum[2] = {0.f, 0.f};
#pragma unroll
        for (int nt = 0; nt < 8; nt++)
#pragma unroll
            for (int half = 0; half < 2; half++) {
                float p0 = __expf(sfr[nt][half * 2 + 0] - m_i[half]);
                float p1 = __expf(sfr[nt][half * 2 + 1] - m_i[half]);
                sfr[nt][half * 2 + 0] = p0;
                sfr[nt][half * 2 + 1] = p1;
                psum[half] += p0 + p1;
            }
#pragma unroll
        for (int i = 0; i < 2; i++) {
            float ps = psum[i];
            ps += __shfl_xor_sync(0xffffffffu, ps, 1);
            ps += __shfl_xor_sync(0xffffffffu, ps, 2);
            l_i[i] = l_i[i] * fsc[i] + ps;
        }
#pragma unroll
        for (int nt = 0; nt < 8; nt++) {
            ofr[nt][0] *= fsc[0];
            ofr[nt][1] *= fsc[0];
            ofr[nt][2] *= fsc[1];
            ofr[nt][3] *= fsc[1];
        }

        // ---- O += Ph * Vh (single term) ----
#pragma unroll
        for (int s = 0; s < 4; s++) {
            unsigned pah[4];
            pah[0] = cvt2h(sfr[2 * s][0], sfr[2 * s][1]);
            pah[1] = cvt2h(sfr[2 * s][2], sfr[2 * s][3]);
            pah[2] = cvt2h(sfr[2 * s + 1][0], sfr[2 * s + 1][1]);
            pah[3] = cvt2h(sfr[2 * s + 1][2], sfr[2 * s + 1][3]);
#pragma unroll
            for (int dg = 0; dg < 4; dg++) {
                unsigned h0, h1, h2, h3;
                const int off = (s * 16 + lrow) * AS + dg * 16 + lcol;
                ldsm4t(h0, h1, h2, h3, sptr(bVh + off));
                mmah(ofr[2 * dg], pah, h0, h1);
                mmah(ofr[2 * dg + 1], pah, h2, h3);
            }
        }
        __syncthreads();
        buf ^= 1;
    }

    // ---- write wv (hi only) ----
    const float inv0 = 1.f / l_i[0];
    const float inv1 = 1.f / l_i[1];
#pragma unroll
    for (int nt = 0; nt < 8; nt++) {
        const int d = h * HD + nt * 8 + 2 * t;
#pragma unroll
        for (int half = 0; half < 2; half++) {
            const int r = q0 + wr + g + half * 8;
            const float inv = half ? inv1 : inv0;
            *reinterpret_cast<unsigned*>(g_oh + (size_t)r * DM + d) =
                cvt2h(ofr[nt][half * 2 + 0] * inv, ofr[nt][half * 2 + 1] * inv);
        }
    }
}

// ---------------------------------------------------------------------------
extern "C" void kernel_launch(void* const* d_in, const int* in_sizes, int n_in,
                              void* d_out, int out_size)
{
    const float* x    = (const float*)d_in[0];
    const float* mask = (const float*)d_in[1];
    const float* Wq   = (const float*)d_in[2];
    const float* bq   = (const float*)d_in[3];
    const float* Wk   = (const float*)d_in[4];
    const float* Wv   = (const float*)d_in[5];
    const float* bv   = (const float*)d_in[6];
    const float* Wo   = (const float*)d_in[7];
    const float* bo   = (const float*)d_in[8];
    const float* Zf   = (const float*)d_in[9];
    const float* invf = (const float*)d_in[10];

    float* out = (float*)d_out;                       // [2048, 1024]
    float* qk  = out + (size_t)SQ * DM;               // [16, 2048, 2048]

    const int proj_smem = 2 * 3 * PBUF * 2;           // 61440 B
    const int attn_smem = (18432 + 2 * A_KVB) * 2;    // 73728 B

    static bool attrs_set = false;
    if (!attrs_set) {
        cudaFuncSetAttribute(qkv_gemm, cudaFuncAttributeMaxDynamicSharedMemorySize, proj_smem);
        cudaFuncSetAttribute(out_gemm, cudaFuncAttributeMaxDynamicSharedMemorySize, proj_smem);
        cudaFuncSetAttribute(attn_kernel, cudaFuncAttributeMaxDynamicSharedMemorySize, attn_smem);
        attrs_set = true;
    }

    rope_table<<<256, 256>>>(invf);

    split_all<<<dim3((SQ * DM / 4 + 255) / 256, 5), 256>>>(x, Wq, Wk, Wv, Wo);

    qkv_gemm<<<dim3(DM / 128, SQ / 128, 3), 512, proj_smem>>>(bq, bv);

    attn_kernel<<<dim3(NH, SQ / 128), 256, attn_smem>>>(mask, Zf, qk);

    out_gemm<<<dim3(DM / 128, SQ / 128), 512, proj_smem>>>(bo, out);
}